// round 1
// baseline (speedup 1.0000x reference)
#include <cuda_runtime.h>
#include <math.h>

#define NTOK   16384          // B*S tokens
#define HD     1024           // hidden
#define MD     2048           // expert mid dim
#define NE     16             // experts
#define SEGALN 64             // segment alignment (= BM tile)
#define MAXSLOTS (2*NTOK + NE*SEGALN)   // 33792, padded slot capacity
#define ROWTILES (MAXSLOTS/64)          // 528

// ---------------- scratch (device globals; no allocations allowed) ----------
__device__ int   g_counts[NE];
__device__ int   g_cursor[NE];
__device__ int   g_offsets[NE + 1];
__device__ int   g_slot_token[MAXSLOTS];
__device__ float g_slot_w[MAXSLOTS];
__device__ int   g_top_idx[NTOK * 2];
__device__ float g_top_w[NTOK * 2];
__device__ float g_Hbuf[(size_t)MAXSLOTS * MD];   // fc1 output (relu'd), fp32

// ---------------- 0) init: reset routing state each launch ------------------
__global__ void init_kernel() {
    int i = blockIdx.x * blockDim.x + threadIdx.x;
    if (i < MAXSLOTS) g_slot_token[i] = -1;
    if (i < NE) g_counts[i] = 0;
}

// ---------------- 1) gate: warp per token, top-2 of 16 logits ---------------
__global__ __launch_bounds__(256) void gate_kernel(
    const float* __restrict__ X, const float* __restrict__ Wg,
    const float* __restrict__ bg)
{
    int warp = (blockIdx.x * blockDim.x + threadIdx.x) >> 5;
    int lane = threadIdx.x & 31;
    if (warp >= NTOK) return;
    const float* x = X + (size_t)warp * HD;

    float acc[NE];
    #pragma unroll
    for (int e = 0; e < NE; e++) acc[e] = 0.f;

    for (int h = lane; h < HD; h += 32) {
        float xv = x[h];
        const float* wr = Wg + h * NE;
        #pragma unroll
        for (int e = 0; e < NE; e++) acc[e] += xv * wr[e];
    }
    #pragma unroll
    for (int off = 16; off > 0; off >>= 1) {
        #pragma unroll
        for (int e = 0; e < NE; e++)
            acc[e] += __shfl_down_sync(0xffffffffu, acc[e], off);
    }
    if (lane == 0) {
        float lg[NE];
        #pragma unroll
        for (int e = 0; e < NE; e++) lg[e] = acc[e] + bg[e];
        // top-2 (first-index-wins on ties, matching jax top_k)
        int e0 = 0;
        #pragma unroll
        for (int e = 1; e < NE; e++) if (lg[e] > lg[e0]) e0 = e;
        int e1 = (e0 == 0) ? 1 : 0;
        #pragma unroll
        for (int e = 0; e < NE; e++)
            if (e != e0 && lg[e] > lg[e1]) e1 = e;
        // renormalized softmax top-2 weights: w0 = 1/(1+exp(l1-l0))
        float d = expf(lg[e1] - lg[e0]);
        float w0 = 1.0f / (1.0f + d);
        float w1 = 1.0f - w0;
        g_top_idx[2 * warp + 0] = e0;  g_top_w[2 * warp + 0] = w0;
        g_top_idx[2 * warp + 1] = e1;  g_top_w[2 * warp + 1] = w1;
        atomicAdd(&g_counts[e0], 1);
        atomicAdd(&g_counts[e1], 1);
    }
}

// ---------------- 2) scan: aligned segment offsets (16 entries) -------------
__global__ void scan_kernel() {
    int off = 0;
    for (int e = 0; e < NE; e++) {
        g_offsets[e] = off;
        g_cursor[e]  = off;
        off = (off + g_counts[e] + (SEGALN - 1)) & ~(SEGALN - 1);
    }
    g_offsets[NE] = off;
}

// ---------------- 3) scatter tokens into per-expert slot lists --------------
__global__ void scatter_kernel() {
    int t = blockIdx.x * blockDim.x + threadIdx.x;
    if (t >= NTOK) return;
    #pragma unroll
    for (int k = 0; k < 2; k++) {
        int e = g_top_idx[2 * t + k];
        int pos = atomicAdd(&g_cursor[e], 1);
        g_slot_token[pos] = t;
        g_slot_w[pos]     = g_top_w[2 * t + k];
    }
}

// ---------------- 4) fc1: H = relu(Xg @ W1[e] + b1[e]) ----------------------
// 64x64x16 tile, 256 threads, 4x4 per thread.
__global__ __launch_bounds__(256) void fc1_kernel(
    const float* __restrict__ X, const float* __restrict__ W1,
    const float* __restrict__ b1)
{
    __shared__ float As[16][64];   // k-major
    __shared__ float Bs[16][64];
    __shared__ int   stok[64];

    int row0 = blockIdx.y * 64;
    int col0 = blockIdx.x * 64;
    int e = 0;
    while (e < NE - 1 && g_offsets[e + 1] <= row0) e++;

    if (threadIdx.x < 64) stok[threadIdx.x] = g_slot_token[row0 + threadIdx.x];
    __syncthreads();

    const float* Wp = W1 + (size_t)e * HD * MD + col0;
    int tx = threadIdx.x & 15, ty = threadIdx.x >> 4;

    float acc[4][4];
    #pragma unroll
    for (int i = 0; i < 4; i++)
        #pragma unroll
        for (int j = 0; j < 4; j++) acc[i][j] = 0.f;

    int ar = threadIdx.x >> 2;          // 0..63 row within tile
    int ak = (threadIdx.x & 3) * 4;     // 0,4,8,12
    int bk = threadIdx.x >> 4;          // 0..15
    int bn = (threadIdx.x & 15) * 4;    // 0..60

    for (int k0 = 0; k0 < HD; k0 += 16) {
        int tok = stok[ar];
        float4 av = (tok >= 0)
            ? *(const float4*)(X + (size_t)tok * HD + k0 + ak)
            : make_float4(0.f, 0.f, 0.f, 0.f);
        float4 bv = *(const float4*)(Wp + (size_t)(k0 + bk) * MD + bn);
        As[ak + 0][ar] = av.x; As[ak + 1][ar] = av.y;
        As[ak + 2][ar] = av.z; As[ak + 3][ar] = av.w;
        *(float4*)&Bs[bk][bn] = bv;
        __syncthreads();
        #pragma unroll
        for (int kk = 0; kk < 16; kk++) {
            float4 a = *(float4*)&As[kk][ty * 4];
            float4 b = *(float4*)&Bs[kk][tx * 4];
            float aa[4] = {a.x, a.y, a.z, a.w};
            float bb[4] = {b.x, b.y, b.z, b.w};
            #pragma unroll
            for (int i = 0; i < 4; i++)
                #pragma unroll
                for (int j = 0; j < 4; j++) acc[i][j] += aa[i] * bb[j];
        }
        __syncthreads();
    }

    float4 bias = *(const float4*)(b1 + e * MD + col0 + tx * 4);
    float bb[4] = {bias.x, bias.y, bias.z, bias.w};
    #pragma unroll
    for (int i = 0; i < 4; i++) {
        int row = row0 + ty * 4 + i;
        float4 v;
        v.x = fmaxf(acc[i][0] + bb[0], 0.f);
        v.y = fmaxf(acc[i][1] + bb[1], 0.f);
        v.z = fmaxf(acc[i][2] + bb[2], 0.f);
        v.w = fmaxf(acc[i][3] + bb[3], 0.f);
        *(float4*)&g_Hbuf[(size_t)row * MD + col0 + tx * 4] = v;
    }
}

// ---------------- 5) fc2: out[tok] += w * (H @ W2[e] + b2[e]) ---------------
__global__ __launch_bounds__(256) void fc2_kernel(
    const float* __restrict__ W2, const float* __restrict__ b2,
    float* __restrict__ out)
{
    __shared__ float As[16][64];
    __shared__ float Bs[16][64];
    __shared__ int   stok[64];
    __shared__ float sw[64];

    int row0 = blockIdx.y * 64;
    int col0 = blockIdx.x * 64;
    int e = 0;
    while (e < NE - 1 && g_offsets[e + 1] <= row0) e++;

    if (threadIdx.x < 64) {
        stok[threadIdx.x] = g_slot_token[row0 + threadIdx.x];
        sw[threadIdx.x]   = g_slot_w[row0 + threadIdx.x];
    }
    __syncthreads();

    const float* Wp = W2 + (size_t)e * MD * HD + col0;
    int tx = threadIdx.x & 15, ty = threadIdx.x >> 4;

    float acc[4][4];
    #pragma unroll
    for (int i = 0; i < 4; i++)
        #pragma unroll
        for (int j = 0; j < 4; j++) acc[i][j] = 0.f;

    int ar = threadIdx.x >> 2;
    int ak = (threadIdx.x & 3) * 4;
    int bk = threadIdx.x >> 4;
    int bn = (threadIdx.x & 15) * 4;

    for (int k0 = 0; k0 < MD; k0 += 16) {
        float4 av = *(const float4*)&g_Hbuf[(size_t)(row0 + ar) * MD + k0 + ak];
        float4 bv = *(const float4*)(Wp + (size_t)(k0 + bk) * HD + bn);
        As[ak + 0][ar] = av.x; As[ak + 1][ar] = av.y;
        As[ak + 2][ar] = av.z; As[ak + 3][ar] = av.w;
        *(float4*)&Bs[bk][bn] = bv;
        __syncthreads();
        #pragma unroll
        for (int kk = 0; kk < 16; kk++) {
            float4 a = *(float4*)&As[kk][ty * 4];
            float4 b = *(float4*)&Bs[kk][tx * 4];
            float aa[4] = {a.x, a.y, a.z, a.w};
            float bb[4] = {b.x, b.y, b.z, b.w};
            #pragma unroll
            for (int i = 0; i < 4; i++)
                #pragma unroll
                for (int j = 0; j < 4; j++) acc[i][j] += aa[i] * bb[j];
        }
        __syncthreads();
    }

    float4 bias = *(const float4*)(b2 + e * HD + col0 + tx * 4);
    float bb[4] = {bias.x, bias.y, bias.z, bias.w};
    #pragma unroll
    for (int i = 0; i < 4; i++) {
        int r = ty * 4 + i;
        int tok = stok[r];
        if (tok < 0) continue;
        float w = sw[r];
        float* op = out + (size_t)tok * HD + col0 + tx * 4;
        #pragma unroll
        for (int j = 0; j < 4; j++)
            atomicAdd(op + j, w * (acc[i][j] + bb[j]));
    }
}

// ---------------- launch ----------------------------------------------------
extern "C" void kernel_launch(void* const* d_in, const int* in_sizes, int n_in,
                              void* d_out, int out_size)
{
    const float* X  = (const float*)d_in[0];
    const float* Wg = (const float*)d_in[1];
    const float* bg = (const float*)d_in[2];
    const float* W1 = (const float*)d_in[3];
    const float* b1 = (const float*)d_in[4];
    const float* W2 = (const float*)d_in[5];
    const float* b2 = (const float*)d_in[6];
    float* out = (float*)d_out;

    // atomics accumulate across graph replays -> zero output every launch
    cudaMemsetAsync(out, 0, sizeof(float) * (size_t)NTOK * HD);

    init_kernel<<<(MAXSLOTS + 255) / 256, 256>>>();
    gate_kernel<<<(NTOK * 32 + 255) / 256, 256>>>(X, Wg, bg);
    scan_kernel<<<1, 1>>>();
    scatter_kernel<<<(NTOK + 255) / 256, 256>>>();
    fc1_kernel<<<dim3(MD / 64, ROWTILES), 256>>>(X, W1, b1);
    fc2_kernel<<<dim3(HD / 64, ROWTILES), 256>>>(W2, b2, out);
}

// round 5
// speedup vs baseline: 1.5759x; 1.5759x over previous
#include <cuda_runtime.h>
#include <cuda_bf16.h>
#include <cstdint>
#include <math.h>

#define NTOK   16384
#define HD     1024
#define MD     2048
#define NE     16
#define SEGALN 64
#define MAXSLOTS (2*NTOK + NE*SEGALN)   // 33792
#define ROWT     (MAXSLOTS/64)          // 528
#define SSTR   17                       // smem pair-stride (16 pairs + 1 pad)

// ---------------- device scratch (round-1 set only) ----------------
__device__ int   g_counts[NE];
__device__ int   g_cursor[NE];
__device__ int   g_offsets[NE + 1];
__device__ int   g_slot_token[MAXSLOTS];
__device__ float g_slot_w[MAXSLOTS];
__device__ int   g_top_idx[NTOK * 2];
__device__ float g_top_w[NTOK * 2];
__device__ float g_Hbuf[(size_t)MAXSLOTS * MD];   // fc1 output, plain fp32

// ---------------- helpers ----------------
// pack two consecutive-k fp32 values into bf16 hi-pair and lo-pair registers
__device__ __forceinline__ void split2(float f0, float f1, uint32_t& hp, uint32_t& lp) {
    __nv_bfloat16 h0 = __float2bfloat16(f0);
    __nv_bfloat16 h1 = __float2bfloat16(f1);
    __nv_bfloat16 l0 = __float2bfloat16(f0 - __bfloat162float(h0));
    __nv_bfloat16 l1 = __float2bfloat16(f1 - __bfloat162float(h1));
    hp = (uint32_t)__bfloat16_as_ushort(h0) | ((uint32_t)__bfloat16_as_ushort(h1) << 16);
    lp = (uint32_t)__bfloat16_as_ushort(l0) | ((uint32_t)__bfloat16_as_ushort(l1) << 16);
}

__device__ __forceinline__ void mma_bf16(float* c, const uint32_t* a, const uint32_t* b) {
    asm volatile("mma.sync.aligned.m16n8k16.row.col.f32.bf16.bf16.f32 "
        "{%0,%1,%2,%3},{%4,%5,%6,%7},{%8,%9},{%0,%1,%2,%3};"
        : "+f"(c[0]), "+f"(c[1]), "+f"(c[2]), "+f"(c[3])
        : "r"(a[0]), "r"(a[1]), "r"(a[2]), "r"(a[3]), "r"(b[0]), "r"(b[1]));
}

// ---------------- routing kernels (verified round 1, unchanged) -------------
__global__ void init_kernel() {
    int i = blockIdx.x * blockDim.x + threadIdx.x;
    if (i < MAXSLOTS) g_slot_token[i] = -1;
    if (i < NE) g_counts[i] = 0;
}

__global__ __launch_bounds__(256) void gate_kernel(
    const float* __restrict__ X, const float* __restrict__ Wg,
    const float* __restrict__ bg)
{
    int warp = (blockIdx.x * blockDim.x + threadIdx.x) >> 5;
    int lane = threadIdx.x & 31;
    if (warp >= NTOK) return;
    const float* x = X + (size_t)warp * HD;

    float acc[NE];
    #pragma unroll
    for (int e = 0; e < NE; e++) acc[e] = 0.f;
    for (int h = lane; h < HD; h += 32) {
        float xv = x[h];
        const float* wr = Wg + h * NE;
        #pragma unroll
        for (int e = 0; e < NE; e++) acc[e] += xv * wr[e];
    }
    #pragma unroll
    for (int off = 16; off > 0; off >>= 1)
        #pragma unroll
        for (int e = 0; e < NE; e++)
            acc[e] += __shfl_down_sync(0xffffffffu, acc[e], off);
    if (lane == 0) {
        float lg[NE];
        #pragma unroll
        for (int e = 0; e < NE; e++) lg[e] = acc[e] + bg[e];
        int e0 = 0;
        #pragma unroll
        for (int e = 1; e < NE; e++) if (lg[e] > lg[e0]) e0 = e;
        int e1 = (e0 == 0) ? 1 : 0;
        #pragma unroll
        for (int e = 0; e < NE; e++)
            if (e != e0 && lg[e] > lg[e1]) e1 = e;
        float d = expf(lg[e1] - lg[e0]);
        float w0 = 1.0f / (1.0f + d);
        g_top_idx[2 * warp + 0] = e0;  g_top_w[2 * warp + 0] = w0;
        g_top_idx[2 * warp + 1] = e1;  g_top_w[2 * warp + 1] = 1.0f - w0;
        atomicAdd(&g_counts[e0], 1);
        atomicAdd(&g_counts[e1], 1);
    }
}

__global__ void scan_kernel() {
    int off = 0;
    for (int e = 0; e < NE; e++) {
        g_offsets[e] = off;
        g_cursor[e]  = off;
        off = (off + g_counts[e] + (SEGALN - 1)) & ~(SEGALN - 1);
    }
    g_offsets[NE] = off;
}

__global__ void scatter_kernel() {
    int t = blockIdx.x * blockDim.x + threadIdx.x;
    if (t >= NTOK) return;
    #pragma unroll
    for (int k = 0; k < 2; k++) {
        int e = g_top_idx[2 * t + k];
        int pos = atomicAdd(&g_cursor[e], 1);
        g_slot_token[pos] = t;
        g_slot_w[pos]     = g_top_w[2 * t + k];
    }
}

// ---------------- shared GEMM tile machinery --------------------------------
// Tiles: BM=64, BN=64, BK=32. 256 threads = 8 warps (4 m-warps x 2 n-warps).
// smem stores bf16 split pairs: [row][pair] with pair index = k/2, stride SSTR.

// load B tile from W[k][n] global (k-major), transposing into sB[n][kpair]
__device__ __forceinline__ void load_B(
    uint32_t* sBhi, uint32_t* sBlo, const float* W, int ldb, int tid)
{
    int bn = tid & 63, kq = tid >> 6;          // kq 0..3 -> k = kq*8..kq*8+7
    const float* bp = W + (size_t)(kq * 8) * ldb + bn;
    float v[8];
    #pragma unroll
    for (int j = 0; j < 8; j++) v[j] = bp[(size_t)j * ldb];
    #pragma unroll
    for (int p = 0; p < 4; p++)
        split2(v[2 * p], v[2 * p + 1],
               sBhi[bn * SSTR + kq * 4 + p], sBlo[bn * SSTR + kq * 4 + p]);
}

// warp compute: one BK=32 chunk, warp tile 16(M) x 32(N), acc[4][4]
__device__ __forceinline__ void warp_step(
    const uint32_t* sAhi, const uint32_t* sAlo,
    const uint32_t* sBhi, const uint32_t* sBlo,
    int wm, int wn, int gid, int tig, float acc[4][4])
{
    #pragma unroll
    for (int s = 0; s < 2; s++) {
        int kp = s * 8 + tig;
        uint32_t ah[4], al[4];
        int r0 = (wm + gid) * SSTR, r1 = (wm + gid + 8) * SSTR;
        ah[0] = sAhi[r0 + kp];     al[0] = sAlo[r0 + kp];
        ah[1] = sAhi[r1 + kp];     al[1] = sAlo[r1 + kp];
        ah[2] = sAhi[r0 + kp + 4]; al[2] = sAlo[r0 + kp + 4];
        ah[3] = sAhi[r1 + kp + 4]; al[3] = sAlo[r1 + kp + 4];
        #pragma unroll
        for (int nt = 0; nt < 4; nt++) {
            int bb = (wn + nt * 8 + gid) * SSTR;
            uint32_t bh[2] = { sBhi[bb + kp], sBhi[bb + kp + 4] };
            uint32_t bl[2] = { sBlo[bb + kp], sBlo[bb + kp + 4] };
            mma_bf16(acc[nt], ah, bh);
            mma_bf16(acc[nt], ah, bl);
            mma_bf16(acc[nt], al, bh);
        }
    }
}

// ---------------- fc1: g_Hbuf = relu(gather(X) @ W1 + b1) -------------------
__global__ __launch_bounds__(256) void fc1_kernel(
    const float* __restrict__ X, const float* __restrict__ W1,
    const float* __restrict__ b1)
{
    __shared__ uint32_t sAhi[64 * SSTR], sAlo[64 * SSTR];
    __shared__ uint32_t sBhi[64 * SSTR], sBlo[64 * SSTR];
    __shared__ int stok[64];

    int tid = threadIdx.x, wid = tid >> 5, lane = tid & 31;
    int gid = lane >> 2, tig = lane & 3;
    int wm = (wid & 3) * 16, wn = (wid >> 2) * 32;
    int row0 = blockIdx.y * 64, col0 = blockIdx.x * 64;

    int e = 0;
    while (e < NE - 1 && g_offsets[e + 1] <= row0) e++;
    if (tid < 64) stok[tid] = g_slot_token[row0 + tid];
    __syncthreads();

    const float* Wp = W1 + (size_t)e * HD * MD + col0;
    int arow = tid >> 2, aq = tid & 3;        // A loader: row 0..63, k-quarter
    int atok = stok[arow];
    const float* asrc = X + (size_t)(atok < 0 ? 0 : atok) * HD + aq * 8;

    float acc[4][4];
    #pragma unroll
    for (int nt = 0; nt < 4; nt++)
        #pragma unroll
        for (int j = 0; j < 4; j++) acc[nt][j] = 0.f;

    for (int k0 = 0; k0 < HD; k0 += 32) {
        float4 v0, v1;
        if (atok >= 0) {
            v0 = *(const float4*)(asrc + k0);
            v1 = *(const float4*)(asrc + k0 + 4);
        } else {
            v0 = make_float4(0.f, 0.f, 0.f, 0.f);
            v1 = v0;
        }
        int pb = arow * SSTR + aq * 4;
        split2(v0.x, v0.y, sAhi[pb + 0], sAlo[pb + 0]);
        split2(v0.z, v0.w, sAhi[pb + 1], sAlo[pb + 1]);
        split2(v1.x, v1.y, sAhi[pb + 2], sAlo[pb + 2]);
        split2(v1.z, v1.w, sAhi[pb + 3], sAlo[pb + 3]);
        load_B(sBhi, sBlo, Wp + (size_t)k0 * MD, MD, tid);
        __syncthreads();
        warp_step(sAhi, sAlo, sBhi, sBlo, wm, wn, gid, tig, acc);
        __syncthreads();
    }

    int r = row0 + wm + gid;
    #pragma unroll
    for (int nt = 0; nt < 4; nt++) {
        int col = col0 + wn + nt * 8 + tig * 2;
        float bb0 = b1[e * MD + col], bb1 = b1[e * MD + col + 1];
        float2 lo, hi;
        lo.x = fmaxf(acc[nt][0] + bb0, 0.f);
        lo.y = fmaxf(acc[nt][1] + bb1, 0.f);
        hi.x = fmaxf(acc[nt][2] + bb0, 0.f);
        hi.y = fmaxf(acc[nt][3] + bb1, 0.f);
        *(float2*)&g_Hbuf[(size_t)r * MD + col]       = lo;
        *(float2*)&g_Hbuf[(size_t)(r + 8) * MD + col] = hi;
    }
}

// ---------------- fc2: out[tok] += w * (g_Hbuf @ W2 + b2) -------------------
__global__ __launch_bounds__(256) void fc2_kernel(
    const float* __restrict__ W2, const float* __restrict__ b2,
    float* __restrict__ out)
{
    __shared__ uint32_t sAhi[64 * SSTR], sAlo[64 * SSTR];
    __shared__ uint32_t sBhi[64 * SSTR], sBlo[64 * SSTR];
    __shared__ int   stok[64];
    __shared__ float sw[64];

    int tid = threadIdx.x, wid = tid >> 5, lane = tid & 31;
    int gid = lane >> 2, tig = lane & 3;
    int wm = (wid & 3) * 16, wn = (wid >> 2) * 32;
    int row0 = blockIdx.y * 64, col0 = blockIdx.x * 64;

    int e = 0;
    while (e < NE - 1 && g_offsets[e + 1] <= row0) e++;
    if (tid < 64) {
        stok[tid] = g_slot_token[row0 + tid];
        sw[tid]   = g_slot_w[row0 + tid];
    }
    __syncthreads();

    const float* Wp = W2 + (size_t)e * MD * HD + col0;
    int arow = tid >> 2, aq = tid & 3;
    const float* asrc = g_Hbuf + (size_t)(row0 + arow) * MD + aq * 8;

    float acc[4][4];
    #pragma unroll
    for (int nt = 0; nt < 4; nt++)
        #pragma unroll
        for (int j = 0; j < 4; j++) acc[nt][j] = 0.f;

    for (int k0 = 0; k0 < MD; k0 += 32) {
        float4 v0 = *(const float4*)(asrc + k0);
        float4 v1 = *(const float4*)(asrc + k0 + 4);
        int pb = arow * SSTR + aq * 4;
        split2(v0.x, v0.y, sAhi[pb + 0], sAlo[pb + 0]);
        split2(v0.z, v0.w, sAhi[pb + 1], sAlo[pb + 1]);
        split2(v1.x, v1.y, sAhi[pb + 2], sAlo[pb + 2]);
        split2(v1.z, v1.w, sAhi[pb + 3], sAlo[pb + 3]);
        load_B(sBhi, sBlo, Wp + (size_t)k0 * HD, HD, tid);
        __syncthreads();
        warp_step(sAhi, sAlo, sBhi, sBlo, wm, wn, gid, tig, acc);
        __syncthreads();
    }

    int rA = wm + gid, rB = wm + gid + 8;
    int tokA = stok[rA], tokB = stok[rB];
    float wA = sw[rA], wB = sw[rB];
    #pragma unroll
    for (int nt = 0; nt < 4; nt++) {
        int col = col0 + wn + nt * 8 + tig * 2;
        float bb0 = b2[e * HD + col], bb1 = b2[e * HD + col + 1];
        if (tokA >= 0) {
            float* op = out + (size_t)tokA * HD + col;
            atomicAdd(op,     wA * (acc[nt][0] + bb0));
            atomicAdd(op + 1, wA * (acc[nt][1] + bb1));
        }
        if (tokB >= 0) {
            float* op = out + (size_t)tokB * HD + col;
            atomicAdd(op,     wB * (acc[nt][2] + bb0));
            atomicAdd(op + 1, wB * (acc[nt][3] + bb1));
        }
    }
}

// ---------------- launch ----------------------------------------------------
extern "C" void kernel_launch(void* const* d_in, const int* in_sizes, int n_in,
                              void* d_out, int out_size)
{
    const float* X  = (const float*)d_in[0];
    const float* Wg = (const float*)d_in[1];
    const float* bg = (const float*)d_in[2];
    const float* W1 = (const float*)d_in[3];
    const float* b1 = (const float*)d_in[4];
    const float* W2 = (const float*)d_in[5];
    const float* b2 = (const float*)d_in[6];
    float* out = (float*)d_out;

    cudaMemsetAsync(out, 0, sizeof(float) * (size_t)NTOK * HD);

    init_kernel<<<(MAXSLOTS + 255) / 256, 256>>>();
    gate_kernel<<<(NTOK * 32 + 255) / 256, 256>>>(X, Wg, bg);
    scan_kernel<<<1, 1>>>();
    scatter_kernel<<<(NTOK + 255) / 256, 256>>>();

    fc1_kernel<<<dim3(MD / 64, ROWT), 256>>>(X, W1, b1);
    fc2_kernel<<<dim3(HD / 64, ROWT), 256>>>(W2, b2, out);
}

// round 6
// speedup vs baseline: 1.8320x; 1.1626x over previous
#include <cuda_runtime.h>
#include <cuda_bf16.h>
#include <cstdint>
#include <math.h>

#define NTOK   16384
#define HD     1024
#define MD     2048
#define NE     16
#define SEGALN 128
#define MAXSLOTS (2*NTOK + NE*SEGALN)   // 34816
#define ROWT     (MAXSLOTS/128)         // 272
#define SSTR   17                       // smem pair-stride (16 pairs + 1 pad)

// ---------------- device scratch ----------------
__device__ int   g_counts[NE];
__device__ int   g_cursor[NE];
__device__ int   g_offsets[NE + 1];
__device__ int   g_slot_token[MAXSLOTS];
__device__ float g_slot_w[MAXSLOTS];
__device__ int   g_top_idx[NTOK * 2];
__device__ float g_top_w[NTOK * 2];
__device__ float g_Hbuf[(size_t)MAXSLOTS * MD];   // fc1 output, plain fp32

// ---------------- helpers ----------------
__device__ __forceinline__ void split2(float f0, float f1, uint32_t& hp, uint32_t& lp) {
    __nv_bfloat16 h0 = __float2bfloat16(f0);
    __nv_bfloat16 h1 = __float2bfloat16(f1);
    __nv_bfloat16 l0 = __float2bfloat16(f0 - __bfloat162float(h0));
    __nv_bfloat16 l1 = __float2bfloat16(f1 - __bfloat162float(h1));
    hp = (uint32_t)__bfloat16_as_ushort(h0) | ((uint32_t)__bfloat16_as_ushort(h1) << 16);
    lp = (uint32_t)__bfloat16_as_ushort(l0) | ((uint32_t)__bfloat16_as_ushort(l1) << 16);
}

__device__ __forceinline__ void mma_bf16(float* c, const uint32_t* a, const uint32_t* b) {
    asm volatile("mma.sync.aligned.m16n8k16.row.col.f32.bf16.bf16.f32 "
        "{%0,%1,%2,%3},{%4,%5,%6,%7},{%8,%9},{%0,%1,%2,%3};"
        : "+f"(c[0]), "+f"(c[1]), "+f"(c[2]), "+f"(c[3])
        : "r"(a[0]), "r"(a[1]), "r"(a[2]), "r"(a[3]), "r"(b[0]), "r"(b[1]));
}

// ---------------- routing kernels (verified, unchanged) ---------------------
__global__ void init_kernel() {
    int i = blockIdx.x * blockDim.x + threadIdx.x;
    if (i < MAXSLOTS) g_slot_token[i] = -1;
    if (i < NE) g_counts[i] = 0;
}

__global__ __launch_bounds__(256) void gate_kernel(
    const float* __restrict__ X, const float* __restrict__ Wg,
    const float* __restrict__ bg)
{
    int warp = (blockIdx.x * blockDim.x + threadIdx.x) >> 5;
    int lane = threadIdx.x & 31;
    if (warp >= NTOK) return;
    const float* x = X + (size_t)warp * HD;

    float acc[NE];
    #pragma unroll
    for (int e = 0; e < NE; e++) acc[e] = 0.f;
    for (int h = lane; h < HD; h += 32) {
        float xv = x[h];
        const float* wr = Wg + h * NE;
        #pragma unroll
        for (int e = 0; e < NE; e++) acc[e] += xv * wr[e];
    }
    #pragma unroll
    for (int off = 16; off > 0; off >>= 1)
        #pragma unroll
        for (int e = 0; e < NE; e++)
            acc[e] += __shfl_down_sync(0xffffffffu, acc[e], off);
    if (lane == 0) {
        float lg[NE];
        #pragma unroll
        for (int e = 0; e < NE; e++) lg[e] = acc[e] + bg[e];
        int e0 = 0;
        #pragma unroll
        for (int e = 1; e < NE; e++) if (lg[e] > lg[e0]) e0 = e;
        int e1 = (e0 == 0) ? 1 : 0;
        #pragma unroll
        for (int e = 0; e < NE; e++)
            if (e != e0 && lg[e] > lg[e1]) e1 = e;
        float d = expf(lg[e1] - lg[e0]);
        float w0 = 1.0f / (1.0f + d);
        g_top_idx[2 * warp + 0] = e0;  g_top_w[2 * warp + 0] = w0;
        g_top_idx[2 * warp + 1] = e1;  g_top_w[2 * warp + 1] = 1.0f - w0;
        atomicAdd(&g_counts[e0], 1);
        atomicAdd(&g_counts[e1], 1);
    }
}

__global__ void scan_kernel() {
    int off = 0;
    for (int e = 0; e < NE; e++) {
        g_offsets[e] = off;
        g_cursor[e]  = off;
        off = (off + g_counts[e] + (SEGALN - 1)) & ~(SEGALN - 1);
    }
    g_offsets[NE] = off;
}

__global__ void scatter_kernel() {
    int t = blockIdx.x * blockDim.x + threadIdx.x;
    if (t >= NTOK) return;
    #pragma unroll
    for (int k = 0; k < 2; k++) {
        int e = g_top_idx[2 * t + k];
        int pos = atomicAdd(&g_cursor[e], 1);
        g_slot_token[pos] = t;
        g_slot_w[pos]     = g_top_w[2 * t + k];
    }
}

// ---------------- GEMM machinery: 128x128x32, 8 warps (2m x 4n) -------------
// A loader: thread -> (row = tid>>1, half = tid&1), 16 floats (k half*16..+15)
// B loader: thread -> (col = tid&127, kq = tid>>7), 16 floats (k kq*16..+15)

__device__ __forceinline__ void store_A(
    uint32_t* sAhi, uint32_t* sAlo, const float* aR, int arow, int ahalf)
{
    int pb = arow * SSTR + ahalf * 8;
    #pragma unroll
    for (int p = 0; p < 8; p++)
        split2(aR[2 * p], aR[2 * p + 1], sAhi[pb + p], sAlo[pb + p]);
}
__device__ __forceinline__ void store_B(
    uint32_t* sBhi, uint32_t* sBlo, const float* bR, int bn, int bkq)
{
    int pb = bn * SSTR + bkq * 8;
    #pragma unroll
    for (int p = 0; p < 8; p++)
        split2(bR[2 * p], bR[2 * p + 1], sBhi[pb + p], sBlo[pb + p]);
}

// warp compute: one BK=32 chunk, warp tile 64(M) x 32(N), acc[4][4][4]
__device__ __forceinline__ void warp_step(
    const uint32_t* sAhi, const uint32_t* sAlo,
    const uint32_t* sBhi, const uint32_t* sBlo,
    int m0, int n0, int gid, int tig, float acc[4][4][4])
{
    #pragma unroll
    for (int s = 0; s < 2; s++) {
        int kp = s * 8 + tig;
        uint32_t ah[4][4], al[4][4], bh[4][2], bl[4][2];
        #pragma unroll
        for (int mt = 0; mt < 4; mt++) {
            int b0 = (m0 + mt * 16 + gid) * SSTR + kp;
            int b1 = b0 + 8 * SSTR;
            ah[mt][0] = sAhi[b0];     al[mt][0] = sAlo[b0];
            ah[mt][1] = sAhi[b1];     al[mt][1] = sAlo[b1];
            ah[mt][2] = sAhi[b0 + 4]; al[mt][2] = sAlo[b0 + 4];
            ah[mt][3] = sAhi[b1 + 4]; al[mt][3] = sAlo[b1 + 4];
        }
        #pragma unroll
        for (int nt = 0; nt < 4; nt++) {
            int bb = (n0 + nt * 8 + gid) * SSTR + kp;
            bh[nt][0] = sBhi[bb]; bh[nt][1] = sBhi[bb + 4];
            bl[nt][0] = sBlo[bb]; bl[nt][1] = sBlo[bb + 4];
        }
        #pragma unroll
        for (int mt = 0; mt < 4; mt++)
            #pragma unroll
            for (int nt = 0; nt < 4; nt++) {
                mma_bf16(acc[mt][nt], ah[mt], bh[nt]);
                mma_bf16(acc[mt][nt], ah[mt], bl[nt]);
                mma_bf16(acc[mt][nt], al[mt], bh[nt]);
            }
    }
}

// ---------------- fc1: g_Hbuf = relu(gather(X) @ W1 + b1) -------------------
__global__ __launch_bounds__(256) void fc1_kernel(
    const float* __restrict__ X, const float* __restrict__ W1,
    const float* __restrict__ b1)
{
    __shared__ uint32_t sAhi[128 * SSTR], sAlo[128 * SSTR];
    __shared__ uint32_t sBhi[128 * SSTR], sBlo[128 * SSTR];
    __shared__ int stok[128];

    int tid = threadIdx.x, wid = tid >> 5, lane = tid & 31;
    int gid = lane >> 2, tig = lane & 3;
    int m0 = (wid >> 2) * 64, n0 = (wid & 3) * 32;
    int row0 = blockIdx.y * 128, col0 = blockIdx.x * 128;

    int e = 0;
    while (e < NE - 1 && g_offsets[e + 1] <= row0) e++;
    if (tid < 128) stok[tid] = g_slot_token[row0 + tid];
    __syncthreads();

    int arow = tid >> 1, ahalf = tid & 1;
    int atok = stok[arow];
    const float* asrc = X + (size_t)(atok < 0 ? 0 : atok) * HD + ahalf * 16;
    int bn = tid & 127, bkq = tid >> 7;
    const float* bsrc = W1 + (size_t)e * HD * MD + col0 + bn;

    float acc[4][4][4];
    #pragma unroll
    for (int mt = 0; mt < 4; mt++)
        #pragma unroll
        for (int nt = 0; nt < 4; nt++)
            #pragma unroll
            for (int j = 0; j < 4; j++) acc[mt][nt][j] = 0.f;

    float aR[16], bR[16];
    const int NI = HD / 32;

    // prologue: load chunk 0
    #pragma unroll
    for (int j = 0; j < 4; j++) {
        float4 v = (atok >= 0) ? *(const float4*)(asrc + j * 4)
                               : make_float4(0.f, 0.f, 0.f, 0.f);
        aR[4*j] = v.x; aR[4*j+1] = v.y; aR[4*j+2] = v.z; aR[4*j+3] = v.w;
    }
    #pragma unroll
    for (int j = 0; j < 16; j++)
        bR[j] = bsrc[(size_t)(bkq * 16 + j) * MD];

    for (int it = 0; it < NI; it++) {
        store_A(sAhi, sAlo, aR, arow, ahalf);
        store_B(sBhi, sBlo, bR, bn, bkq);
        __syncthreads();
        if (it + 1 < NI) {
            int k0 = (it + 1) * 32;
            #pragma unroll
            for (int j = 0; j < 4; j++) {
                float4 v = (atok >= 0) ? *(const float4*)(asrc + k0 + j * 4)
                                       : make_float4(0.f, 0.f, 0.f, 0.f);
                aR[4*j] = v.x; aR[4*j+1] = v.y; aR[4*j+2] = v.z; aR[4*j+3] = v.w;
            }
            #pragma unroll
            for (int j = 0; j < 16; j++)
                bR[j] = bsrc[(size_t)(k0 + bkq * 16 + j) * MD];
        }
        warp_step(sAhi, sAlo, sBhi, sBlo, m0, n0, gid, tig, acc);
        __syncthreads();
    }

    #pragma unroll
    for (int mt = 0; mt < 4; mt++) {
        int r = row0 + m0 + mt * 16 + gid;
        #pragma unroll
        for (int nt = 0; nt < 4; nt++) {
            int col = col0 + n0 + nt * 8 + tig * 2;
            float bb0 = b1[e * MD + col], bb1 = b1[e * MD + col + 1];
            float2 lo, hi;
            lo.x = fmaxf(acc[mt][nt][0] + bb0, 0.f);
            lo.y = fmaxf(acc[mt][nt][1] + bb1, 0.f);
            hi.x = fmaxf(acc[mt][nt][2] + bb0, 0.f);
            hi.y = fmaxf(acc[mt][nt][3] + bb1, 0.f);
            *(float2*)&g_Hbuf[(size_t)r * MD + col]       = lo;
            *(float2*)&g_Hbuf[(size_t)(r + 8) * MD + col] = hi;
        }
    }
}

// ---------------- fc2: out[tok] += w * (g_Hbuf @ W2 + b2) -------------------
__global__ __launch_bounds__(256) void fc2_kernel(
    const float* __restrict__ W2, const float* __restrict__ b2,
    float* __restrict__ out)
{
    __shared__ uint32_t sAhi[128 * SSTR], sAlo[128 * SSTR];
    __shared__ uint32_t sBhi[128 * SSTR], sBlo[128 * SSTR];
    __shared__ int   stok[128];
    __shared__ float sw[128];

    int tid = threadIdx.x, wid = tid >> 5, lane = tid & 31;
    int gid = lane >> 2, tig = lane & 3;
    int m0 = (wid >> 2) * 64, n0 = (wid & 3) * 32;
    int row0 = blockIdx.y * 128, col0 = blockIdx.x * 128;

    int e = 0;
    while (e < NE - 1 && g_offsets[e + 1] <= row0) e++;
    if (tid < 128) {
        stok[tid] = g_slot_token[row0 + tid];
        sw[tid]   = g_slot_w[row0 + tid];
    }
    __syncthreads();

    int arow = tid >> 1, ahalf = tid & 1;
    const float* asrc = g_Hbuf + (size_t)(row0 + arow) * MD + ahalf * 16;
    int bn = tid & 127, bkq = tid >> 7;
    const float* bsrc = W2 + (size_t)e * MD * HD + col0 + bn;

    float acc[4][4][4];
    #pragma unroll
    for (int mt = 0; mt < 4; mt++)
        #pragma unroll
        for (int nt = 0; nt < 4; nt++)
            #pragma unroll
            for (int j = 0; j < 4; j++) acc[mt][nt][j] = 0.f;

    float aR[16], bR[16];
    const int NI = MD / 32;

    #pragma unroll
    for (int j = 0; j < 4; j++) {
        float4 v = *(const float4*)(asrc + j * 4);
        aR[4*j] = v.x; aR[4*j+1] = v.y; aR[4*j+2] = v.z; aR[4*j+3] = v.w;
    }
    #pragma unroll
    for (int j = 0; j < 16; j++)
        bR[j] = bsrc[(size_t)(bkq * 16 + j) * HD];

    for (int it = 0; it < NI; it++) {
        store_A(sAhi, sAlo, aR, arow, ahalf);
        store_B(sBhi, sBlo, bR, bn, bkq);
        __syncthreads();
        if (it + 1 < NI) {
            int k0 = (it + 1) * 32;
            #pragma unroll
            for (int j = 0; j < 4; j++) {
                float4 v = *(const float4*)(asrc + k0 + j * 4);
                aR[4*j] = v.x; aR[4*j+1] = v.y; aR[4*j+2] = v.z; aR[4*j+3] = v.w;
            }
            #pragma unroll
            for (int j = 0; j < 16; j++)
                bR[j] = bsrc[(size_t)(k0 + bkq * 16 + j) * HD];
        }
        warp_step(sAhi, sAlo, sBhi, sBlo, m0, n0, gid, tig, acc);
        __syncthreads();
    }

    #pragma unroll
    for (int mt = 0; mt < 4; mt++) {
        int rA = m0 + mt * 16 + gid, rB = rA + 8;
        int tokA = stok[rA], tokB = stok[rB];
        float wA = sw[rA], wB = sw[rB];
        #pragma unroll
        for (int nt = 0; nt < 4; nt++) {
            int col = col0 + n0 + nt * 8 + tig * 2;
            float bb0 = b2[e * HD + col], bb1 = b2[e * HD + col + 1];
            if (tokA >= 0) {
                float* op = out + (size_t)tokA * HD + col;
                atomicAdd(op,     wA * (acc[mt][nt][0] + bb0));
                atomicAdd(op + 1, wA * (acc[mt][nt][1] + bb1));
            }
            if (tokB >= 0) {
                float* op = out + (size_t)tokB * HD + col;
                atomicAdd(op,     wB * (acc[mt][nt][2] + bb0));
                atomicAdd(op + 1, wB * (acc[mt][nt][3] + bb1));
            }
        }
    }
}

// ---------------- launch ----------------------------------------------------
extern "C" void kernel_launch(void* const* d_in, const int* in_sizes, int n_in,
                              void* d_out, int out_size)
{
    const float* X  = (const float*)d_in[0];
    const float* Wg = (const float*)d_in[1];
    const float* bg = (const float*)d_in[2];
    const float* W1 = (const float*)d_in[3];
    const float* b1 = (const float*)d_in[4];
    const float* W2 = (const float*)d_in[5];
    const float* b2 = (const float*)d_in[6];
    float* out = (float*)d_out;

    cudaMemsetAsync(out, 0, sizeof(float) * (size_t)NTOK * HD);

    init_kernel<<<(MAXSLOTS + 255) / 256, 256>>>();
    gate_kernel<<<(NTOK * 32 + 255) / 256, 256>>>(X, Wg, bg);
    scan_kernel<<<1, 1>>>();
    scatter_kernel<<<(NTOK + 255) / 256, 256>>>();

    fc1_kernel<<<dim3(MD / 128, ROWT), 256>>>(X, W1, b1);
    fc2_kernel<<<dim3(HD / 128, ROWT), 256>>>(W2, b2, out);
}

// round 7
// speedup vs baseline: 2.2434x; 1.2245x over previous
#include <cuda_runtime.h>
#include <cuda_fp16.h>
#include <cstdint>
#include <math.h>

#define NTOK   16384
#define HD     1024
#define MD     2048
#define NE     16
#define SEGALN 128
#define MAXSLOTS (2*NTOK + NE*SEGALN)   // 34816
#define ROWT     (MAXSLOTS/128)         // 272
#define SSTR   17                       // smem pair-stride (16 pairs + 1 pad)

// ---------------- device scratch ----------------
__device__ int   g_counts[NE];
__device__ int   g_cursor[NE];
__device__ int   g_offsets[NE + 1];
__device__ int   g_slot_token[MAXSLOTS];
__device__ float g_slot_w[MAXSLOTS];
__device__ int   g_top_idx[NTOK * 2];
__device__ float g_top_w[NTOK * 2];
__device__ float g_Hbuf[(size_t)MAXSLOTS * MD];   // fc1 output, plain fp32

// ---------------- helpers ----------------
// pack two fp32 into one fp16x2 register (rn rounding)
__device__ __forceinline__ uint32_t pack2h(float f0, float f1) {
    __half2 h = __floats2half2_rn(f0, f1);
    return *(uint32_t*)&h;
}
// split two fp32 into fp16 hi-pair and lo-pair
__device__ __forceinline__ void splitB2(float f0, float f1, uint32_t& hp, uint32_t& lp) {
    __half h0 = __float2half_rn(f0);
    __half h1 = __float2half_rn(f1);
    __half l0 = __float2half_rn(f0 - __half2float(h0));
    __half l1 = __float2half_rn(f1 - __half2float(h1));
    hp = (uint32_t)__half_as_ushort(h0) | ((uint32_t)__half_as_ushort(h1) << 16);
    lp = (uint32_t)__half_as_ushort(l0) | ((uint32_t)__half_as_ushort(l1) << 16);
}

__device__ __forceinline__ void mma_f16(float* c, const uint32_t* a, const uint32_t* b) {
    asm volatile("mma.sync.aligned.m16n8k16.row.col.f32.f16.f16.f32 "
        "{%0,%1,%2,%3},{%4,%5,%6,%7},{%8,%9},{%0,%1,%2,%3};"
        : "+f"(c[0]), "+f"(c[1]), "+f"(c[2]), "+f"(c[3])
        : "r"(a[0]), "r"(a[1]), "r"(a[2]), "r"(a[3]), "r"(b[0]), "r"(b[1]));
}

// ---------------- routing kernels (verified, unchanged) ---------------------
__global__ void init_kernel() {
    int i = blockIdx.x * blockDim.x + threadIdx.x;
    if (i < MAXSLOTS) g_slot_token[i] = -1;
    if (i < NE) g_counts[i] = 0;
}

__global__ __launch_bounds__(256) void gate_kernel(
    const float* __restrict__ X, const float* __restrict__ Wg,
    const float* __restrict__ bg)
{
    int warp = (blockIdx.x * blockDim.x + threadIdx.x) >> 5;
    int lane = threadIdx.x & 31;
    if (warp >= NTOK) return;
    const float* x = X + (size_t)warp * HD;

    float acc[NE];
    #pragma unroll
    for (int e = 0; e < NE; e++) acc[e] = 0.f;
    for (int h = lane; h < HD; h += 32) {
        float xv = x[h];
        const float* wr = Wg + h * NE;
        #pragma unroll
        for (int e = 0; e < NE; e++) acc[e] += xv * wr[e];
    }
    #pragma unroll
    for (int off = 16; off > 0; off >>= 1)
        #pragma unroll
        for (int e = 0; e < NE; e++)
            acc[e] += __shfl_down_sync(0xffffffffu, acc[e], off);
    if (lane == 0) {
        float lg[NE];
        #pragma unroll
        for (int e = 0; e < NE; e++) lg[e] = acc[e] + bg[e];
        int e0 = 0;
        #pragma unroll
        for (int e = 1; e < NE; e++) if (lg[e] > lg[e0]) e0 = e;
        int e1 = (e0 == 0) ? 1 : 0;
        #pragma unroll
        for (int e = 0; e < NE; e++)
            if (e != e0 && lg[e] > lg[e1]) e1 = e;
        float d = expf(lg[e1] - lg[e0]);
        float w0 = 1.0f / (1.0f + d);
        g_top_idx[2 * warp + 0] = e0;  g_top_w[2 * warp + 0] = w0;
        g_top_idx[2 * warp + 1] = e1;  g_top_w[2 * warp + 1] = 1.0f - w0;
        atomicAdd(&g_counts[e0], 1);
        atomicAdd(&g_counts[e1], 1);
    }
}

__global__ void scan_kernel() {
    int off = 0;
    for (int e = 0; e < NE; e++) {
        g_offsets[e] = off;
        g_cursor[e]  = off;
        off = (off + g_counts[e] + (SEGALN - 1)) & ~(SEGALN - 1);
    }
    g_offsets[NE] = off;
}

__global__ void scatter_kernel() {
    int t = blockIdx.x * blockDim.x + threadIdx.x;
    if (t >= NTOK) return;
    #pragma unroll
    for (int k = 0; k < 2; k++) {
        int e = g_top_idx[2 * t + k];
        int pos = atomicAdd(&g_cursor[e], 1);
        g_slot_token[pos] = t;
        g_slot_w[pos]     = g_top_w[2 * t + k];
    }
}

// ---------------- GEMM machinery: 128x128x32, 8 warps (2m x 4n) -------------
// A: single fp16 plane (rn-rounded). B: split fp16 hi+lo planes.
// A loader: thread -> (row = tid>>1, half = tid&1), 16 floats
// B loader: thread -> (col = tid&127, kq = tid>>7), 16 floats

__device__ __forceinline__ void store_A(
    uint32_t* sA, const float* aR, int arow, int ahalf)
{
    int pb = arow * SSTR + ahalf * 8;
    #pragma unroll
    for (int p = 0; p < 8; p++)
        sA[pb + p] = pack2h(aR[2 * p], aR[2 * p + 1]);
}
__device__ __forceinline__ void store_B(
    uint32_t* sBhi, uint32_t* sBlo, const float* bR, int bn, int bkq)
{
    int pb = bn * SSTR + bkq * 8;
    #pragma unroll
    for (int p = 0; p < 8; p++)
        splitB2(bR[2 * p], bR[2 * p + 1], sBhi[pb + p], sBlo[pb + p]);
}

// warp compute: one BK=32 chunk, warp tile 64(M) x 32(N), acc[4][4][4]
__device__ __forceinline__ void warp_step(
    const uint32_t* sA, const uint32_t* sBhi, const uint32_t* sBlo,
    int m0, int n0, int gid, int tig, float acc[4][4][4])
{
    #pragma unroll
    for (int s = 0; s < 2; s++) {
        int kp = s * 8 + tig;
        uint32_t af[4][4], bh[4][2], bl[4][2];
        #pragma unroll
        for (int mt = 0; mt < 4; mt++) {
            int b0 = (m0 + mt * 16 + gid) * SSTR + kp;
            int b1 = b0 + 8 * SSTR;
            af[mt][0] = sA[b0];
            af[mt][1] = sA[b1];
            af[mt][2] = sA[b0 + 4];
            af[mt][3] = sA[b1 + 4];
        }
        #pragma unroll
        for (int nt = 0; nt < 4; nt++) {
            int bb = (n0 + nt * 8 + gid) * SSTR + kp;
            bh[nt][0] = sBhi[bb]; bh[nt][1] = sBhi[bb + 4];
            bl[nt][0] = sBlo[bb]; bl[nt][1] = sBlo[bb + 4];
        }
        #pragma unroll
        for (int mt = 0; mt < 4; mt++)
            #pragma unroll
            for (int nt = 0; nt < 4; nt++) {
                mma_f16(acc[mt][nt], af[mt], bh[nt]);
                mma_f16(acc[mt][nt], af[mt], bl[nt]);
            }
    }
}

// ---------------- fc1: g_Hbuf = relu(gather(X) @ W1 + b1) -------------------
__global__ __launch_bounds__(256) void fc1_kernel(
    const float* __restrict__ X, const float* __restrict__ W1,
    const float* __restrict__ b1)
{
    __shared__ uint32_t sA[128 * SSTR];
    __shared__ uint32_t sBhi[128 * SSTR], sBlo[128 * SSTR];
    __shared__ int stok[128];

    int tid = threadIdx.x, wid = tid >> 5, lane = tid & 31;
    int gid = lane >> 2, tig = lane & 3;
    int m0 = (wid >> 2) * 64, n0 = (wid & 3) * 32;
    int row0 = blockIdx.y * 128, col0 = blockIdx.x * 128;

    int e = 0;
    while (e < NE - 1 && g_offsets[e + 1] <= row0) e++;
    if (tid < 128) stok[tid] = g_slot_token[row0 + tid];
    __syncthreads();

    int arow = tid >> 1, ahalf = tid & 1;
    int atok = stok[arow];
    const float* asrc = X + (size_t)(atok < 0 ? 0 : atok) * HD + ahalf * 16;
    int bn = tid & 127, bkq = tid >> 7;
    const float* bsrc = W1 + (size_t)e * HD * MD + col0 + bn;

    float acc[4][4][4];
    #pragma unroll
    for (int mt = 0; mt < 4; mt++)
        #pragma unroll
        for (int nt = 0; nt < 4; nt++)
            #pragma unroll
            for (int j = 0; j < 4; j++) acc[mt][nt][j] = 0.f;

    float aR[16], bR[16];
    const int NI = HD / 32;

    #pragma unroll
    for (int j = 0; j < 4; j++) {
        float4 v = (atok >= 0) ? *(const float4*)(asrc + j * 4)
                               : make_float4(0.f, 0.f, 0.f, 0.f);
        aR[4*j] = v.x; aR[4*j+1] = v.y; aR[4*j+2] = v.z; aR[4*j+3] = v.w;
    }
    #pragma unroll
    for (int j = 0; j < 16; j++)
        bR[j] = bsrc[(size_t)(bkq * 16 + j) * MD];

    for (int it = 0; it < NI; it++) {
        store_A(sA, aR, arow, ahalf);
        store_B(sBhi, sBlo, bR, bn, bkq);
        __syncthreads();
        if (it + 1 < NI) {
            int k0 = (it + 1) * 32;
            #pragma unroll
            for (int j = 0; j < 4; j++) {
                float4 v = (atok >= 0) ? *(const float4*)(asrc + k0 + j * 4)
                                       : make_float4(0.f, 0.f, 0.f, 0.f);
                aR[4*j] = v.x; aR[4*j+1] = v.y; aR[4*j+2] = v.z; aR[4*j+3] = v.w;
            }
            #pragma unroll
            for (int j = 0; j < 16; j++)
                bR[j] = bsrc[(size_t)(k0 + bkq * 16 + j) * MD];
        }
        warp_step(sA, sBhi, sBlo, m0, n0, gid, tig, acc);
        __syncthreads();
    }

    #pragma unroll
    for (int mt = 0; mt < 4; mt++) {
        int r = row0 + m0 + mt * 16 + gid;
        #pragma unroll
        for (int nt = 0; nt < 4; nt++) {
            int col = col0 + n0 + nt * 8 + tig * 2;
            float bb0 = b1[e * MD + col], bb1 = b1[e * MD + col + 1];
            float2 lo, hi;
            lo.x = fmaxf(acc[mt][nt][0] + bb0, 0.f);
            lo.y = fmaxf(acc[mt][nt][1] + bb1, 0.f);
            hi.x = fmaxf(acc[mt][nt][2] + bb0, 0.f);
            hi.y = fmaxf(acc[mt][nt][3] + bb1, 0.f);
            *(float2*)&g_Hbuf[(size_t)r * MD + col]       = lo;
            *(float2*)&g_Hbuf[(size_t)(r + 8) * MD + col] = hi;
        }
    }
}

// ---------------- fc2: out[tok] += w * (g_Hbuf @ W2 + b2) -------------------
__global__ __launch_bounds__(256) void fc2_kernel(
    const float* __restrict__ W2, const float* __restrict__ b2,
    float* __restrict__ out)
{
    __shared__ uint32_t sA[128 * SSTR];
    __shared__ uint32_t sBhi[128 * SSTR], sBlo[128 * SSTR];
    __shared__ int   stok[128];
    __shared__ float sw[128];

    int tid = threadIdx.x, wid = tid >> 5, lane = tid & 31;
    int gid = lane >> 2, tig = lane & 3;
    int m0 = (wid >> 2) * 64, n0 = (wid & 3) * 32;
    int row0 = blockIdx.y * 128, col0 = blockIdx.x * 128;

    int e = 0;
    while (e < NE - 1 && g_offsets[e + 1] <= row0) e++;
    if (tid < 128) {
        stok[tid] = g_slot_token[row0 + tid];
        sw[tid]   = g_slot_w[row0 + tid];
    }
    __syncthreads();

    int arow = tid >> 1, ahalf = tid & 1;
    const float* asrc = g_Hbuf + (size_t)(row0 + arow) * MD + ahalf * 16;
    int bn = tid & 127, bkq = tid >> 7;
    const float* bsrc = W2 + (size_t)e * MD * HD + col0 + bn;

    float acc[4][4][4];
    #pragma unroll
    for (int mt = 0; mt < 4; mt++)
        #pragma unroll
        for (int nt = 0; nt < 4; nt++)
            #pragma unroll
            for (int j = 0; j < 4; j++) acc[mt][nt][j] = 0.f;

    float aR[16], bR[16];
    const int NI = MD / 32;

    #pragma unroll
    for (int j = 0; j < 4; j++) {
        float4 v = *(const float4*)(asrc + j * 4);
        aR[4*j] = v.x; aR[4*j+1] = v.y; aR[4*j+2] = v.z; aR[4*j+3] = v.w;
    }
    #pragma unroll
    for (int j = 0; j < 16; j++)
        bR[j] = bsrc[(size_t)(bkq * 16 + j) * HD];

    for (int it = 0; it < NI; it++) {
        store_A(sA, aR, arow, ahalf);
        store_B(sBhi, sBlo, bR, bn, bkq);
        __syncthreads();
        if (it + 1 < NI) {
            int k0 = (it + 1) * 32;
            #pragma unroll
            for (int j = 0; j < 4; j++) {
                float4 v = *(const float4*)(asrc + k0 + j * 4);
                aR[4*j] = v.x; aR[4*j+1] = v.y; aR[4*j+2] = v.z; aR[4*j+3] = v.w;
            }
            #pragma unroll
            for (int j = 0; j < 16; j++)
                bR[j] = bsrc[(size_t)(k0 + bkq * 16 + j) * HD];
        }
        warp_step(sA, sBhi, sBlo, m0, n0, gid, tig, acc);
        __syncthreads();
    }

    #pragma unroll
    for (int mt = 0; mt < 4; mt++) {
        int rA = m0 + mt * 16 + gid, rB = rA + 8;
        int tokA = stok[rA], tokB = stok[rB];
        float wA = sw[rA], wB = sw[rB];
        #pragma unroll
        for (int nt = 0; nt < 4; nt++) {
            int col = col0 + n0 + nt * 8 + tig * 2;
            float bb0 = b2[e * HD + col], bb1 = b2[e * HD + col + 1];
            if (tokA >= 0) {
                float* op = out + (size_t)tokA * HD + col;
                atomicAdd(op,     wA * (acc[mt][nt][0] + bb0));
                atomicAdd(op + 1, wA * (acc[mt][nt][1] + bb1));
            }
            if (tokB >= 0) {
                float* op = out + (size_t)tokB * HD + col;
                atomicAdd(op,     wB * (acc[mt][nt][2] + bb0));
                atomicAdd(op + 1, wB * (acc[mt][nt][3] + bb1));
            }
        }
    }
}

// ---------------- launch ----------------------------------------------------
extern "C" void kernel_launch(void* const* d_in, const int* in_sizes, int n_in,
                              void* d_out, int out_size)
{
    const float* X  = (const float*)d_in[0];
    const float* Wg = (const float*)d_in[1];
    const float* bg = (const float*)d_in[2];
    const float* W1 = (const float*)d_in[3];
    const float* b1 = (const float*)d_in[4];
    const float* W2 = (const float*)d_in[5];
    const float* b2 = (const float*)d_in[6];
    float* out = (float*)d_out;

    cudaMemsetAsync(out, 0, sizeof(float) * (size_t)NTOK * HD);

    init_kernel<<<(MAXSLOTS + 255) / 256, 256>>>();
    gate_kernel<<<(NTOK * 32 + 255) / 256, 256>>>(X, Wg, bg);
    scan_kernel<<<1, 1>>>();
    scatter_kernel<<<(NTOK + 255) / 256, 256>>>();

    fc1_kernel<<<dim3(MD / 128, ROWT), 256>>>(X, W1, b1);
    fc2_kernel<<<dim3(HD / 128, ROWT), 256>>>(W2, b2, out);
}

// round 8
// speedup vs baseline: 3.4761x; 1.5495x over previous
#include <cuda_runtime.h>
#include <cuda_fp16.h>
#include <cstdint>
#include <math.h>

#define NTOK   16384
#define HD     1024
#define MD     2048
#define NE     16
#define SEGALN 128
#define MAXSLOTS (2*NTOK + NE*SEGALN)   // 34816
#define ROWT     (MAXSLOTS/128)         // 272
#define SSTR   17                       // smem pair-stride (16 pairs + 1 pad)

// ---------------- device scratch ----------------
__device__ int   g_counts[NE];
__device__ int   g_cursor[NE];
__device__ int   g_offsets[NE + 1];
__device__ int   g_slot_token[MAXSLOTS];
__device__ float g_slot_w[MAXSLOTS];
__device__ int   g_top_idx[NTOK * 2];
__device__ float g_top_w[NTOK * 2];
__device__ float g_Hbuf[(size_t)MAXSLOTS * MD];   // fc1 output, plain fp32

// ---------------- helpers ----------------
__device__ __forceinline__ uint32_t pack2h(float f0, float f1) {
    __half2 h = __floats2half2_rn(f0, f1);
    return *(uint32_t*)&h;
}

__device__ __forceinline__ void mma_f16(float* c, const uint32_t* a, const uint32_t* b) {
    asm volatile("mma.sync.aligned.m16n8k16.row.col.f32.f16.f16.f32 "
        "{%0,%1,%2,%3},{%4,%5,%6,%7},{%8,%9},{%0,%1,%2,%3};"
        : "+f"(c[0]), "+f"(c[1]), "+f"(c[2]), "+f"(c[3])
        : "r"(a[0]), "r"(a[1]), "r"(a[2]), "r"(a[3]), "r"(b[0]), "r"(b[1]));
}

// ---------------- routing kernels (verified, unchanged) ---------------------
__global__ void init_kernel() {
    int i = blockIdx.x * blockDim.x + threadIdx.x;
    if (i < MAXSLOTS) g_slot_token[i] = -1;
    if (i < NE) g_counts[i] = 0;
}

__global__ __launch_bounds__(256) void gate_kernel(
    const float* __restrict__ X, const float* __restrict__ Wg,
    const float* __restrict__ bg)
{
    int warp = (blockIdx.x * blockDim.x + threadIdx.x) >> 5;
    int lane = threadIdx.x & 31;
    if (warp >= NTOK) return;
    const float* x = X + (size_t)warp * HD;

    float acc[NE];
    #pragma unroll
    for (int e = 0; e < NE; e++) acc[e] = 0.f;
    for (int h = lane; h < HD; h += 32) {
        float xv = x[h];
        const float* wr = Wg + h * NE;
        #pragma unroll
        for (int e = 0; e < NE; e++) acc[e] += xv * wr[e];
    }
    #pragma unroll
    for (int off = 16; off > 0; off >>= 1)
        #pragma unroll
        for (int e = 0; e < NE; e++)
            acc[e] += __shfl_down_sync(0xffffffffu, acc[e], off);
    if (lane == 0) {
        float lg[NE];
        #pragma unroll
        for (int e = 0; e < NE; e++) lg[e] = acc[e] + bg[e];
        int e0 = 0;
        #pragma unroll
        for (int e = 1; e < NE; e++) if (lg[e] > lg[e0]) e0 = e;
        int e1 = (e0 == 0) ? 1 : 0;
        #pragma unroll
        for (int e = 0; e < NE; e++)
            if (e != e0 && lg[e] > lg[e1]) e1 = e;
        float d = expf(lg[e1] - lg[e0]);
        float w0 = 1.0f / (1.0f + d);
        g_top_idx[2 * warp + 0] = e0;  g_top_w[2 * warp + 0] = w0;
        g_top_idx[2 * warp + 1] = e1;  g_top_w[2 * warp + 1] = 1.0f - w0;
        atomicAdd(&g_counts[e0], 1);
        atomicAdd(&g_counts[e1], 1);
    }
}

__global__ void scan_kernel() {
    int off = 0;
    for (int e = 0; e < NE; e++) {
        g_offsets[e] = off;
        g_cursor[e]  = off;
        off = (off + g_counts[e] + (SEGALN - 1)) & ~(SEGALN - 1);
    }
    g_offsets[NE] = off;
}

__global__ void scatter_kernel() {
    int t = blockIdx.x * blockDim.x + threadIdx.x;
    if (t >= NTOK) return;
    #pragma unroll
    for (int k = 0; k < 2; k++) {
        int e = g_top_idx[2 * t + k];
        int pos = atomicAdd(&g_cursor[e], 1);
        g_slot_token[pos] = t;
        g_slot_w[pos]     = g_top_w[2 * t + k];
    }
}

// ---------------- GEMM machinery: 128x128x32, 8 warps (2m x 4n) -------------
// A and B both single fp16 planes (rn-rounded).
// A loader: thread -> (row = tid>>1, half = tid&1), 16 floats
// B loader: thread -> (col = tid&127, kq = tid>>7), 16 floats

__device__ __forceinline__ void store_half_row(
    uint32_t* s, const float* r, int row, int half)
{
    int pb = row * SSTR + half * 8;
    #pragma unroll
    for (int p = 0; p < 8; p++)
        s[pb + p] = pack2h(r[2 * p], r[2 * p + 1]);
}

// warp compute: one BK=32 chunk, warp tile 64(M) x 32(N), acc[4][4][4]
__device__ __forceinline__ void warp_step(
    const uint32_t* sA, const uint32_t* sB,
    int m0, int n0, int gid, int tig, float acc[4][4][4])
{
    #pragma unroll
    for (int s = 0; s < 2; s++) {
        int kp = s * 8 + tig;
        uint32_t af[4][4], bf[4][2];
        #pragma unroll
        for (int mt = 0; mt < 4; mt++) {
            int b0 = (m0 + mt * 16 + gid) * SSTR + kp;
            int b1 = b0 + 8 * SSTR;
            af[mt][0] = sA[b0];
            af[mt][1] = sA[b1];
            af[mt][2] = sA[b0 + 4];
            af[mt][3] = sA[b1 + 4];
        }
        #pragma unroll
        for (int nt = 0; nt < 4; nt++) {
            int bb = (n0 + nt * 8 + gid) * SSTR + kp;
            bf[nt][0] = sB[bb]; bf[nt][1] = sB[bb + 4];
        }
        #pragma unroll
        for (int mt = 0; mt < 4; mt++)
            #pragma unroll
            for (int nt = 0; nt < 4; nt++)
                mma_f16(acc[mt][nt], af[mt], bf[nt]);
    }
}

// ---------------- fc1: g_Hbuf = relu(gather(X) @ W1 + b1) -------------------
__global__ __launch_bounds__(256) void fc1_kernel(
    const float* __restrict__ X, const float* __restrict__ W1,
    const float* __restrict__ b1)
{
    __shared__ uint32_t sA[128 * SSTR];
    __shared__ uint32_t sB[128 * SSTR];
    __shared__ int stok[128];

    int tid = threadIdx.x, wid = tid >> 5, lane = tid & 31;
    int gid = lane >> 2, tig = lane & 3;
    int m0 = (wid >> 2) * 64, n0 = (wid & 3) * 32;
    int row0 = blockIdx.y * 128, col0 = blockIdx.x * 128;

    int e = 0;
    while (e < NE - 1 && g_offsets[e + 1] <= row0) e++;
    if (tid < 128) stok[tid] = g_slot_token[row0 + tid];
    __syncthreads();

    int arow = tid >> 1, ahalf = tid & 1;
    int atok = stok[arow];
    const float* asrc = X + (size_t)(atok < 0 ? 0 : atok) * HD + ahalf * 16;
    int bn = tid & 127, bkq = tid >> 7;
    const float* bsrc = W1 + (size_t)e * HD * MD + col0 + bn;

    float acc[4][4][4];
    #pragma unroll
    for (int mt = 0; mt < 4; mt++)
        #pragma unroll
        for (int nt = 0; nt < 4; nt++)
            #pragma unroll
            for (int j = 0; j < 4; j++) acc[mt][nt][j] = 0.f;

    float aR[16], bR[16];
    const int NI = HD / 32;

    #pragma unroll
    for (int j = 0; j < 4; j++) {
        float4 v = (atok >= 0) ? *(const float4*)(asrc + j * 4)
                               : make_float4(0.f, 0.f, 0.f, 0.f);
        aR[4*j] = v.x; aR[4*j+1] = v.y; aR[4*j+2] = v.z; aR[4*j+3] = v.w;
    }
    #pragma unroll
    for (int j = 0; j < 16; j++)
        bR[j] = bsrc[(size_t)(bkq * 16 + j) * MD];

    for (int it = 0; it < NI; it++) {
        store_half_row(sA, aR, arow, ahalf);
        store_half_row(sB, bR, bn, bkq);
        __syncthreads();
        if (it + 1 < NI) {
            int k0 = (it + 1) * 32;
            #pragma unroll
            for (int j = 0; j < 4; j++) {
                float4 v = (atok >= 0) ? *(const float4*)(asrc + k0 + j * 4)
                                       : make_float4(0.f, 0.f, 0.f, 0.f);
                aR[4*j] = v.x; aR[4*j+1] = v.y; aR[4*j+2] = v.z; aR[4*j+3] = v.w;
            }
            #pragma unroll
            for (int j = 0; j < 16; j++)
                bR[j] = bsrc[(size_t)(k0 + bkq * 16 + j) * MD];
        }
        warp_step(sA, sB, m0, n0, gid, tig, acc);
        __syncthreads();
    }

    #pragma unroll
    for (int mt = 0; mt < 4; mt++) {
        int r = row0 + m0 + mt * 16 + gid;
        #pragma unroll
        for (int nt = 0; nt < 4; nt++) {
            int col = col0 + n0 + nt * 8 + tig * 2;
            float bb0 = b1[e * MD + col], bb1 = b1[e * MD + col + 1];
            float2 lo, hi;
            lo.x = fmaxf(acc[mt][nt][0] + bb0, 0.f);
            lo.y = fmaxf(acc[mt][nt][1] + bb1, 0.f);
            hi.x = fmaxf(acc[mt][nt][2] + bb0, 0.f);
            hi.y = fmaxf(acc[mt][nt][3] + bb1, 0.f);
            *(float2*)&g_Hbuf[(size_t)r * MD + col]       = lo;
            *(float2*)&g_Hbuf[(size_t)(r + 8) * MD + col] = hi;
        }
    }
}

// ---------------- fc2: out[tok] += w * (g_Hbuf @ W2 + b2) -------------------
__global__ __launch_bounds__(256) void fc2_kernel(
    const float* __restrict__ W2, const float* __restrict__ b2,
    float* __restrict__ out)
{
    __shared__ uint32_t sA[128 * SSTR];
    __shared__ uint32_t sB[128 * SSTR];
    __shared__ int   stok[128];
    __shared__ float sw[128];

    int tid = threadIdx.x, wid = tid >> 5, lane = tid & 31;
    int gid = lane >> 2, tig = lane & 3;
    int m0 = (wid >> 2) * 64, n0 = (wid & 3) * 32;
    int row0 = blockIdx.y * 128, col0 = blockIdx.x * 128;

    int e = 0;
    while (e < NE - 1 && g_offsets[e + 1] <= row0) e++;
    if (tid < 128) {
        stok[tid] = g_slot_token[row0 + tid];
        sw[tid]   = g_slot_w[row0 + tid];
    }
    __syncthreads();

    int arow = tid >> 1, ahalf = tid & 1;
    const float* asrc = g_Hbuf + (size_t)(row0 + arow) * MD + ahalf * 16;
    int bn = tid & 127, bkq = tid >> 7;
    const float* bsrc = W2 + (size_t)e * MD * HD + col0 + bn;

    float acc[4][4][4];
    #pragma unroll
    for (int mt = 0; mt < 4; mt++)
        #pragma unroll
        for (int nt = 0; nt < 4; nt++)
            #pragma unroll
            for (int j = 0; j < 4; j++) acc[mt][nt][j] = 0.f;

    float aR[16], bR[16];
    const int NI = MD / 32;

    #pragma unroll
    for (int j = 0; j < 4; j++) {
        float4 v = *(const float4*)(asrc + j * 4);
        aR[4*j] = v.x; aR[4*j+1] = v.y; aR[4*j+2] = v.z; aR[4*j+3] = v.w;
    }
    #pragma unroll
    for (int j = 0; j < 16; j++)
        bR[j] = bsrc[(size_t)(bkq * 16 + j) * HD];

    for (int it = 0; it < NI; it++) {
        store_half_row(sA, aR, arow, ahalf);
        store_half_row(sB, bR, bn, bkq);
        __syncthreads();
        if (it + 1 < NI) {
            int k0 = (it + 1) * 32;
            #pragma unroll
            for (int j = 0; j < 4; j++) {
                float4 v = *(const float4*)(asrc + k0 + j * 4);
                aR[4*j] = v.x; aR[4*j+1] = v.y; aR[4*j+2] = v.z; aR[4*j+3] = v.w;
            }
            #pragma unroll
            for (int j = 0; j < 16; j++)
                bR[j] = bsrc[(size_t)(k0 + bkq * 16 + j) * HD];
        }
        warp_step(sA, sB, m0, n0, gid, tig, acc);
        __syncthreads();
    }

    #pragma unroll
    for (int mt = 0; mt < 4; mt++) {
        int rA = m0 + mt * 16 + gid, rB = rA + 8;
        int tokA = stok[rA], tokB = stok[rB];
        float wA = sw[rA], wB = sw[rB];
        #pragma unroll
        for (int nt = 0; nt < 4; nt++) {
            int col = col0 + n0 + nt * 8 + tig * 2;
            float bb0 = b2[e * HD + col], bb1 = b2[e * HD + col + 1];
            if (tokA >= 0) {
                float* op = out + (size_t)tokA * HD + col;
                atomicAdd(op,     wA * (acc[mt][nt][0] + bb0));
                atomicAdd(op + 1, wA * (acc[mt][nt][1] + bb1));
            }
            if (tokB >= 0) {
                float* op = out + (size_t)tokB * HD + col;
                atomicAdd(op,     wB * (acc[mt][nt][2] + bb0));
                atomicAdd(op + 1, wB * (acc[mt][nt][3] + bb1));
            }
        }
    }
}

// ---------------- launch ----------------------------------------------------
extern "C" void kernel_launch(void* const* d_in, const int* in_sizes, int n_in,
                              void* d_out, int out_size)
{
    const float* X  = (const float*)d_in[0];
    const float* Wg = (const float*)d_in[1];
    const float* bg = (const float*)d_in[2];
    const float* W1 = (const float*)d_in[3];
    const float* b1 = (const float*)d_in[4];
    const float* W2 = (const float*)d_in[5];
    const float* b2 = (const float*)d_in[6];
    float* out = (float*)d_out;

    cudaMemsetAsync(out, 0, sizeof(float) * (size_t)NTOK * HD);

    init_kernel<<<(MAXSLOTS + 255) / 256, 256>>>();
    gate_kernel<<<(NTOK * 32 + 255) / 256, 256>>>(X, Wg, bg);
    scan_kernel<<<1, 1>>>();
    scatter_kernel<<<(NTOK + 255) / 256, 256>>>();

    fc1_kernel<<<dim3(MD / 128, ROWT), 256>>>(X, W1, b1);
    fc2_kernel<<<dim3(HD / 128, ROWT), 256>>>(W2, b2, out);
}

// round 9
// speedup vs baseline: 4.3815x; 1.2605x over previous
#include <cuda_runtime.h>
#include <cuda_fp16.h>
#include <cstdint>
#include <math.h>

#define NTOK   16384
#define HD     1024
#define MD     2048
#define NE     16
#define SEGALN 128
#define MAXSLOTS (2*NTOK + NE*SEGALN)   // 34816
#define ROWT     (MAXSLOTS/128)         // 272
#define SSTR   20                       // smem pair-stride (16 pairs + 4 pad; 80B rows, 16B-aligned for ldmatrix)

// ---------------- device scratch ----------------
__device__ int   g_counts[NE];
__device__ int   g_cursor[NE];
__device__ int   g_offsets[NE + 1];
__device__ int   g_slot_token[MAXSLOTS];
__device__ float g_slot_w[MAXSLOTS];
__device__ int   g_top_idx[NTOK * 2];
__device__ float g_top_w[NTOK * 2];
__device__ float g_Hbuf[(size_t)MAXSLOTS * MD];   // fc1 output, plain fp32

// ---------------- helpers ----------------
__device__ __forceinline__ uint32_t smem_u32(const void* p) {
    uint32_t a;
    asm("{ .reg .u64 t; cvta.to.shared.u64 t, %1; cvt.u32.u64 %0, t; }" : "=r"(a) : "l"(p));
    return a;
}
__device__ __forceinline__ uint32_t pack2h(float f0, float f1) {
    __half2 h = __floats2half2_rn(f0, f1);
    return *(uint32_t*)&h;
}
__device__ __forceinline__ void mma_f16(float* c, const uint32_t* a, const uint32_t* b) {
    asm volatile("mma.sync.aligned.m16n8k16.row.col.f32.f16.f16.f32 "
        "{%0,%1,%2,%3},{%4,%5,%6,%7},{%8,%9},{%0,%1,%2,%3};"
        : "+f"(c[0]), "+f"(c[1]), "+f"(c[2]), "+f"(c[3])
        : "r"(a[0]), "r"(a[1]), "r"(a[2]), "r"(a[3]), "r"(b[0]), "r"(b[1]));
}
__device__ __forceinline__ void ldsm4(uint32_t& r0, uint32_t& r1, uint32_t& r2, uint32_t& r3,
                                      uint32_t addr) {
    asm volatile("ldmatrix.sync.aligned.m8n8.x4.shared.b16 {%0,%1,%2,%3}, [%4];"
        : "=r"(r0), "=r"(r1), "=r"(r2), "=r"(r3) : "r"(addr));
}

// ---------------- routing kernels (verified, unchanged) ---------------------
__global__ void init_kernel() {
    int i = blockIdx.x * blockDim.x + threadIdx.x;
    if (i < MAXSLOTS) g_slot_token[i] = -1;
    if (i < NE) g_counts[i] = 0;
}

__global__ __launch_bounds__(256) void gate_kernel(
    const float* __restrict__ X, const float* __restrict__ Wg,
    const float* __restrict__ bg)
{
    int warp = (blockIdx.x * blockDim.x + threadIdx.x) >> 5;
    int lane = threadIdx.x & 31;
    if (warp >= NTOK) return;
    const float* x = X + (size_t)warp * HD;

    float acc[NE];
    #pragma unroll
    for (int e = 0; e < NE; e++) acc[e] = 0.f;
    for (int h = lane; h < HD; h += 32) {
        float xv = x[h];
        const float* wr = Wg + h * NE;
        #pragma unroll
        for (int e = 0; e < NE; e++) acc[e] += xv * wr[e];
    }
    #pragma unroll
    for (int off = 16; off > 0; off >>= 1)
        #pragma unroll
        for (int e = 0; e < NE; e++)
            acc[e] += __shfl_down_sync(0xffffffffu, acc[e], off);
    if (lane == 0) {
        float lg[NE];
        #pragma unroll
        for (int e = 0; e < NE; e++) lg[e] = acc[e] + bg[e];
        int e0 = 0;
        #pragma unroll
        for (int e = 1; e < NE; e++) if (lg[e] > lg[e0]) e0 = e;
        int e1 = (e0 == 0) ? 1 : 0;
        #pragma unroll
        for (int e = 0; e < NE; e++)
            if (e != e0 && lg[e] > lg[e1]) e1 = e;
        float d = expf(lg[e1] - lg[e0]);
        float w0 = 1.0f / (1.0f + d);
        g_top_idx[2 * warp + 0] = e0;  g_top_w[2 * warp + 0] = w0;
        g_top_idx[2 * warp + 1] = e1;  g_top_w[2 * warp + 1] = 1.0f - w0;
        atomicAdd(&g_counts[e0], 1);
        atomicAdd(&g_counts[e1], 1);
    }
}

__global__ void scan_kernel() {
    int off = 0;
    for (int e = 0; e < NE; e++) {
        g_offsets[e] = off;
        g_cursor[e]  = off;
        off = (off + g_counts[e] + (SEGALN - 1)) & ~(SEGALN - 1);
    }
    g_offsets[NE] = off;
}

__global__ void scatter_kernel() {
    int t = blockIdx.x * blockDim.x + threadIdx.x;
    if (t >= NTOK) return;
    #pragma unroll
    for (int k = 0; k < 2; k++) {
        int e = g_top_idx[2 * t + k];
        int pos = atomicAdd(&g_cursor[e], 1);
        g_slot_token[pos] = t;
        g_slot_w[pos]     = g_top_w[2 * t + k];
    }
}

// ---------------- GEMM machinery: 128x128x32, 8 warps (2m x 4n) -------------
// A and B both single fp16 planes (rn-rounded), ldmatrix fragment loads.

__device__ __forceinline__ void store_half_row(
    uint32_t* s, const float* r, int row, int half)
{
    int pb = row * SSTR + half * 8;
    #pragma unroll
    for (int p = 0; p < 8; p++)
        s[pb + p] = pack2h(r[2 * p], r[2 * p + 1]);
}

// warp compute: one BK=32 chunk, warp tile 64(M) x 32(N), acc[4][4][4]
__device__ __forceinline__ void warp_step(
    uint32_t sAaddr, uint32_t sBaddr,
    int m0, int n0, int lane, float acc[4][4][4])
{
    int l7 = lane & 7;
    int aRow = l7 + ((lane >> 3) & 1) * 8;      // row offset within m16 tile
    int aKp  = (lane >> 4) * 4;                 // kp offset (0 or 4)
    int bRow = ((lane >> 4) * 8) + l7;          // n offset within n16 pair
    int bKp  = ((lane >> 3) & 1) * 4;
    #pragma unroll
    for (int s = 0; s < 2; s++) {
        uint32_t af[4][4], bf[4][2];
        #pragma unroll
        for (int mt = 0; mt < 4; mt++) {
            uint32_t addr = sAaddr + (uint32_t)(((m0 + mt * 16 + aRow) * SSTR) + s * 8 + aKp) * 4u;
            ldsm4(af[mt][0], af[mt][1], af[mt][2], af[mt][3], addr);
        }
        #pragma unroll
        for (int ntp = 0; ntp < 2; ntp++) {
            uint32_t addr = sBaddr + (uint32_t)(((n0 + ntp * 16 + bRow) * SSTR) + s * 8 + bKp) * 4u;
            ldsm4(bf[2 * ntp][0], bf[2 * ntp][1], bf[2 * ntp + 1][0], bf[2 * ntp + 1][1], addr);
        }
        #pragma unroll
        for (int mt = 0; mt < 4; mt++)
            #pragma unroll
            for (int nt = 0; nt < 4; nt++)
                mma_f16(acc[mt][nt], af[mt], bf[nt]);
    }
}

// ---------------- fc1: g_Hbuf = relu(gather(X) @ W1 + b1) -------------------
__global__ __launch_bounds__(256) void fc1_kernel(
    const float* __restrict__ X, const float* __restrict__ W1,
    const float* __restrict__ b1)
{
    __shared__ __align__(16) uint32_t sA[128 * SSTR];
    __shared__ __align__(16) uint32_t sB[128 * SSTR];
    __shared__ int stok[128];

    int tid = threadIdx.x, wid = tid >> 5, lane = tid & 31;
    int gid = lane >> 2, tig = lane & 3;
    int m0 = (wid >> 2) * 64, n0 = (wid & 3) * 32;
    int row0 = blockIdx.y * 128, col0 = blockIdx.x * 128;

    int e = 0;
    while (e < NE - 1 && g_offsets[e + 1] <= row0) e++;
    if (tid < 128) stok[tid] = g_slot_token[row0 + tid];
    __syncthreads();

    uint32_t sAaddr = smem_u32(sA), sBaddr = smem_u32(sB);
    int arow = tid >> 1, ahalf = tid & 1;
    int atok = stok[arow];
    const float* asrc = X + (size_t)(atok < 0 ? 0 : atok) * HD + ahalf * 16;
    int bn = tid & 127, bkq = tid >> 7;
    const float* bsrc = W1 + (size_t)e * HD * MD + col0 + bn;

    float acc[4][4][4];
    #pragma unroll
    for (int mt = 0; mt < 4; mt++)
        #pragma unroll
        for (int nt = 0; nt < 4; nt++)
            #pragma unroll
            for (int j = 0; j < 4; j++) acc[mt][nt][j] = 0.f;

    float aR[16], bR[16];
    const int NI = HD / 32;

    #pragma unroll
    for (int j = 0; j < 4; j++) {
        float4 v = (atok >= 0) ? *(const float4*)(asrc + j * 4)
                               : make_float4(0.f, 0.f, 0.f, 0.f);
        aR[4*j] = v.x; aR[4*j+1] = v.y; aR[4*j+2] = v.z; aR[4*j+3] = v.w;
    }
    #pragma unroll
    for (int j = 0; j < 16; j++)
        bR[j] = bsrc[(size_t)(bkq * 16 + j) * MD];

    for (int it = 0; it < NI; it++) {
        store_half_row(sA, aR, arow, ahalf);
        store_half_row(sB, bR, bn, bkq);
        __syncthreads();
        if (it + 1 < NI) {
            int k0 = (it + 1) * 32;
            #pragma unroll
            for (int j = 0; j < 4; j++) {
                float4 v = (atok >= 0) ? *(const float4*)(asrc + k0 + j * 4)
                                       : make_float4(0.f, 0.f, 0.f, 0.f);
                aR[4*j] = v.x; aR[4*j+1] = v.y; aR[4*j+2] = v.z; aR[4*j+3] = v.w;
            }
            #pragma unroll
            for (int j = 0; j < 16; j++)
                bR[j] = bsrc[(size_t)(k0 + bkq * 16 + j) * MD];
        }
        warp_step(sAaddr, sBaddr, m0, n0, lane, acc);
        __syncthreads();
    }

    #pragma unroll
    for (int mt = 0; mt < 4; mt++) {
        int r = row0 + m0 + mt * 16 + gid;
        #pragma unroll
        for (int nt = 0; nt < 4; nt++) {
            int col = col0 + n0 + nt * 8 + tig * 2;
            float bb0 = b1[e * MD + col], bb1 = b1[e * MD + col + 1];
            float2 lo, hi;
            lo.x = fmaxf(acc[mt][nt][0] + bb0, 0.f);
            lo.y = fmaxf(acc[mt][nt][1] + bb1, 0.f);
            hi.x = fmaxf(acc[mt][nt][2] + bb0, 0.f);
            hi.y = fmaxf(acc[mt][nt][3] + bb1, 0.f);
            *(float2*)&g_Hbuf[(size_t)r * MD + col]       = lo;
            *(float2*)&g_Hbuf[(size_t)(r + 8) * MD + col] = hi;
        }
    }
}

// ---------------- fc2: out[tok] += w * (g_Hbuf @ W2 + b2) -------------------
__global__ __launch_bounds__(256) void fc2_kernel(
    const float* __restrict__ W2, const float* __restrict__ b2,
    float* __restrict__ out)
{
    __shared__ __align__(16) uint32_t sA[128 * SSTR];
    __shared__ __align__(16) uint32_t sB[128 * SSTR];
    __shared__ int   stok[128];
    __shared__ float sw[128];

    int tid = threadIdx.x, wid = tid >> 5, lane = tid & 31;
    int gid = lane >> 2, tig = lane & 3;
    int m0 = (wid >> 2) * 64, n0 = (wid & 3) * 32;
    int row0 = blockIdx.y * 128, col0 = blockIdx.x * 128;

    int e = 0;
    while (e < NE - 1 && g_offsets[e + 1] <= row0) e++;
    if (tid < 128) {
        stok[tid] = g_slot_token[row0 + tid];
        sw[tid]   = g_slot_w[row0 + tid];
    }
    __syncthreads();

    uint32_t sAaddr = smem_u32(sA), sBaddr = smem_u32(sB);
    int arow = tid >> 1, ahalf = tid & 1;
    const float* asrc = g_Hbuf + (size_t)(row0 + arow) * MD + ahalf * 16;
    int bn = tid & 127, bkq = tid >> 7;
    const float* bsrc = W2 + (size_t)e * MD * HD + col0 + bn;

    float acc[4][4][4];
    #pragma unroll
    for (int mt = 0; mt < 4; mt++)
        #pragma unroll
        for (int nt = 0; nt < 4; nt++)
            #pragma unroll
            for (int j = 0; j < 4; j++) acc[mt][nt][j] = 0.f;

    float aR[16], bR[16];
    const int NI = MD / 32;

    #pragma unroll
    for (int j = 0; j < 4; j++) {
        float4 v = *(const float4*)(asrc + j * 4);
        aR[4*j] = v.x; aR[4*j+1] = v.y; aR[4*j+2] = v.z; aR[4*j+3] = v.w;
    }
    #pragma unroll
    for (int j = 0; j < 16; j++)
        bR[j] = bsrc[(size_t)(bkq * 16 + j) * HD];

    for (int it = 0; it < NI; it++) {
        store_half_row(sA, aR, arow, ahalf);
        store_half_row(sB, bR, bn, bkq);
        __syncthreads();
        if (it + 1 < NI) {
            int k0 = (it + 1) * 32;
            #pragma unroll
            for (int j = 0; j < 4; j++) {
                float4 v = *(const float4*)(asrc + k0 + j * 4);
                aR[4*j] = v.x; aR[4*j+1] = v.y; aR[4*j+2] = v.z; aR[4*j+3] = v.w;
            }
            #pragma unroll
            for (int j = 0; j < 16; j++)
                bR[j] = bsrc[(size_t)(k0 + bkq * 16 + j) * HD];
        }
        warp_step(sAaddr, sBaddr, m0, n0, lane, acc);
        __syncthreads();
    }

    #pragma unroll
    for (int mt = 0; mt < 4; mt++) {
        int rA = m0 + mt * 16 + gid, rB = rA + 8;
        int tokA = stok[rA], tokB = stok[rB];
        float wA = sw[rA], wB = sw[rB];
        #pragma unroll
        for (int nt = 0; nt < 4; nt++) {
            int col = col0 + n0 + nt * 8 + tig * 2;
            float bb0 = b2[e * HD + col], bb1 = b2[e * HD + col + 1];
            if (tokA >= 0) {
                float* op = out + (size_t)tokA * HD + col;
                atomicAdd(op,     wA * (acc[mt][nt][0] + bb0));
                atomicAdd(op + 1, wA * (acc[mt][nt][1] + bb1));
            }
            if (tokB >= 0) {
                float* op = out + (size_t)tokB * HD + col;
                atomicAdd(op,     wB * (acc[mt][nt][2] + bb0));
                atomicAdd(op + 1, wB * (acc[mt][nt][3] + bb1));
            }
        }
    }
}

// ---------------- launch ----------------------------------------------------
extern "C" void kernel_launch(void* const* d_in, const int* in_sizes, int n_in,
                              void* d_out, int out_size)
{
    const float* X  = (const float*)d_in[0];
    const float* Wg = (const float*)d_in[1];
    const float* bg = (const float*)d_in[2];
    const float* W1 = (const float*)d_in[3];
    const float* b1 = (const float*)d_in[4];
    const float* W2 = (const float*)d_in[5];
    const float* b2 = (const float*)d_in[6];
    float* out = (float*)d_out;

    cudaMemsetAsync(out, 0, sizeof(float) * (size_t)NTOK * HD);

    init_kernel<<<(MAXSLOTS + 255) / 256, 256>>>();
    gate_kernel<<<(NTOK * 32 + 255) / 256, 256>>>(X, Wg, bg);
    scan_kernel<<<1, 1>>>();
    scatter_kernel<<<(NTOK + 255) / 256, 256>>>();

    fc1_kernel<<<dim3(MD / 128, ROWT), 256>>>(X, W1, b1);
    fc2_kernel<<<dim3(HD / 128, ROWT), 256>>>(W2, b2, out);
}

// round 12
// speedup vs baseline: 4.7118x; 1.0754x over previous
#include <cuda_runtime.h>
#include <cuda_fp16.h>
#include <cstdint>
#include <math.h>

#define NTOK   16384
#define HD     1024
#define MD     2048
#define NE     16
#define SEGALN 128
#define MAXSLOTS (2*NTOK + NE*SEGALN)   // 34816
#define ROWT     (MAXSLOTS/128)         // 272
#define SSTR   20                       // smem pair-stride (16 pairs + 4 pad; 80B rows)

// ---------------- device scratch ----------------
__device__ int   g_counts[NE];
__device__ int   g_cursor[NE];
__device__ int   g_offsets[NE + 1];
__device__ int   g_slot_token[MAXSLOTS];
__device__ float g_slot_w[MAXSLOTS];
__device__ int   g_top_idx[NTOK * 2];
__device__ float g_top_w[NTOK * 2];
__device__ __half g_Xh [(size_t)NTOK * HD];        // X pre-rounded to fp16
__device__ __half g_W1h[(size_t)NE * HD * MD];     // W1 fp16, same layout
__device__ __half g_W2h[(size_t)NE * MD * HD];     // W2 fp16, same layout
__device__ __half g_Hh [(size_t)MAXSLOTS * MD];    // fc1 output, fp16

// ---------------- helpers ----------------
__device__ __forceinline__ uint32_t smem_u32(const void* p) {
    uint32_t a;
    asm("{ .reg .u64 t; cvta.to.shared.u64 t, %1; cvt.u32.u64 %0, t; }" : "=r"(a) : "l"(p));
    return a;
}
__device__ __forceinline__ uint32_t pack2h(float f0, float f1) {
    __half2 h = __floats2half2_rn(f0, f1);
    return *(uint32_t*)&h;
}
__device__ __forceinline__ void mma_f16(float* c, const uint32_t* a, const uint32_t* b) {
    asm volatile("mma.sync.aligned.m16n8k16.row.col.f32.f16.f16.f32 "
        "{%0,%1,%2,%3},{%4,%5,%6,%7},{%8,%9},{%0,%1,%2,%3};"
        : "+f"(c[0]), "+f"(c[1]), "+f"(c[2]), "+f"(c[3])
        : "r"(a[0]), "r"(a[1]), "r"(a[2]), "r"(a[3]), "r"(b[0]), "r"(b[1]));
}
__device__ __forceinline__ void ldsm4(uint32_t& r0, uint32_t& r1, uint32_t& r2, uint32_t& r3,
                                      uint32_t addr) {
    asm volatile("ldmatrix.sync.aligned.m8n8.x4.shared.b16 {%0,%1,%2,%3}, [%4];"
        : "=r"(r0), "=r"(r1), "=r"(r2), "=r"(r3) : "r"(addr));
}

// ---------------- prep: fp32 -> fp16 elementwise ----------------------------
__global__ __launch_bounds__(256) void f2h_kernel(
    const float* __restrict__ src, __half* __restrict__ dst, int n4)
{
    int i = blockIdx.x * blockDim.x + threadIdx.x;
    if (i >= n4) return;
    float4 v = ((const float4*)src)[i];
    uint2 o;
    o.x = pack2h(v.x, v.y);
    o.y = pack2h(v.z, v.w);
    ((uint2*)dst)[i] = o;
}

// ---------------- routing kernels (verified, unchanged) ---------------------
__global__ void init_kernel() {
    int i = blockIdx.x * blockDim.x + threadIdx.x;
    if (i < MAXSLOTS) g_slot_token[i] = -1;
    if (i < NE) g_counts[i] = 0;
}

__global__ __launch_bounds__(256) void gate_kernel(
    const float* __restrict__ X, const float* __restrict__ Wg,
    const float* __restrict__ bg)
{
    int warp = (blockIdx.x * blockDim.x + threadIdx.x) >> 5;
    int lane = threadIdx.x & 31;
    if (warp >= NTOK) return;
    const float* x = X + (size_t)warp * HD;

    float acc[NE];
    #pragma unroll
    for (int e = 0; e < NE; e++) acc[e] = 0.f;
    for (int h = lane; h < HD; h += 32) {
        float xv = x[h];
        const float* wr = Wg + h * NE;
        #pragma unroll
        for (int e = 0; e < NE; e++) acc[e] += xv * wr[e];
    }
    #pragma unroll
    for (int off = 16; off > 0; off >>= 1)
        #pragma unroll
        for (int e = 0; e < NE; e++)
            acc[e] += __shfl_down_sync(0xffffffffu, acc[e], off);
    if (lane == 0) {
        float lg[NE];
        #pragma unroll
        for (int e = 0; e < NE; e++) lg[e] = acc[e] + bg[e];
        int e0 = 0;
        #pragma unroll
        for (int e = 1; e < NE; e++) if (lg[e] > lg[e0]) e0 = e;
        int e1 = (e0 == 0) ? 1 : 0;
        #pragma unroll
        for (int e = 0; e < NE; e++)
            if (e != e0 && lg[e] > lg[e1]) e1 = e;
        float d = expf(lg[e1] - lg[e0]);
        float w0 = 1.0f / (1.0f + d);
        g_top_idx[2 * warp + 0] = e0;  g_top_w[2 * warp + 0] = w0;
        g_top_idx[2 * warp + 1] = e1;  g_top_w[2 * warp + 1] = 1.0f - w0;
        atomicAdd(&g_counts[e0], 1);
        atomicAdd(&g_counts[e1], 1);
    }
}

__global__ void scan_kernel() {
    int off = 0;
    for (int e = 0; e < NE; e++) {
        g_offsets[e] = off;
        g_cursor[e]  = off;
        off = (off + g_counts[e] + (SEGALN - 1)) & ~(SEGALN - 1);
    }
    g_offsets[NE] = off;
}

__global__ void scatter_kernel() {
    int t = blockIdx.x * blockDim.x + threadIdx.x;
    if (t >= NTOK) return;
    #pragma unroll
    for (int k = 0; k < 2; k++) {
        int e = g_top_idx[2 * t + k];
        int pos = atomicAdd(&g_cursor[e], 1);
        g_slot_token[pos] = t;
        g_slot_w[pos]     = g_top_w[2 * t + k];
    }
}

// ---------------- GEMM machinery: 128x128x32, 8 warps (2m x 4n) -------------
// A and B fp16 in global; smem stores are plain copies.

// warp compute: one BK=32 chunk, warp tile 64(M) x 32(N), acc[4][4][4]
__device__ __forceinline__ void warp_step(
    uint32_t sAaddr, uint32_t sBaddr,
    int m0, int n0, int lane, float acc[4][4][4])
{
    int l7 = lane & 7;
    int aRow = l7 + ((lane >> 3) & 1) * 8;
    int aKp  = (lane >> 4) * 4;
    int bRow = ((lane >> 4) * 8) + l7;
    int bKp  = ((lane >> 3) & 1) * 4;
    #pragma unroll
    for (int s = 0; s < 2; s++) {
        uint32_t af[4][4], bf[4][2];
        #pragma unroll
        for (int mt = 0; mt < 4; mt++) {
            uint32_t addr = sAaddr + (uint32_t)(((m0 + mt * 16 + aRow) * SSTR) + s * 8 + aKp) * 4u;
            ldsm4(af[mt][0], af[mt][1], af[mt][2], af[mt][3], addr);
        }
        #pragma unroll
        for (int ntp = 0; ntp < 2; ntp++) {
            uint32_t addr = sBaddr + (uint32_t)(((n0 + ntp * 16 + bRow) * SSTR) + s * 8 + bKp) * 4u;
            ldsm4(bf[2 * ntp][0], bf[2 * ntp][1], bf[2 * ntp + 1][0], bf[2 * ntp + 1][1], addr);
        }
        #pragma unroll
        for (int mt = 0; mt < 4; mt++)
            #pragma unroll
            for (int nt = 0; nt < 4; nt++)
                mma_f16(acc[mt][nt], af[mt], bf[nt]);
    }
}

// ---------------- fc1: g_Hh = fp16(relu(gather(Xh) @ W1h + b1)) -------------
__global__ __launch_bounds__(256) void fc1_kernel(
    const float* __restrict__ b1)
{
    __shared__ __align__(16) uint32_t sA[128 * SSTR];
    __shared__ __align__(16) uint32_t sB[128 * SSTR];
    __shared__ int stok[128];

    int tid = threadIdx.x, wid = tid >> 5, lane = tid & 31;
    int gid = lane >> 2, tig = lane & 3;
    int m0 = (wid >> 2) * 64, n0 = (wid & 3) * 32;
    int row0 = blockIdx.y * 128, col0 = blockIdx.x * 128;

    int e = 0;
    while (e < NE - 1 && g_offsets[e + 1] <= row0) e++;
    if (tid < 128) stok[tid] = g_slot_token[row0 + tid];
    __syncthreads();

    uint32_t sAaddr = smem_u32(sA), sBaddr = smem_u32(sB);
    // A loader: thread -> (row = tid>>1, half = tid&1), 16 halves = 2x uint4
    int arow = tid >> 1, ahalf = tid & 1;
    int atok = stok[arow];
    const __half* asrc = g_Xh + (size_t)(atok < 0 ? 0 : atok) * HD + ahalf * 16;
    // B loader: thread -> (col = tid&127, kq = tid>>7), 16 k-rows (1 half each)
    int bn = tid & 127, bkq = tid >> 7;
    const __half* bsrc = g_W1h + (size_t)e * HD * MD + col0 + bn;

    float acc[4][4][4];
    #pragma unroll
    for (int mt = 0; mt < 4; mt++)
        #pragma unroll
        for (int nt = 0; nt < 4; nt++)
            #pragma unroll
            for (int j = 0; j < 4; j++) acc[mt][nt][j] = 0.f;

    uint4 aV0, aV1;
    uint16_t bV[16];
    const int NI = HD / 32;

    // prologue: load chunk 0
    if (atok >= 0) {
        aV0 = *(const uint4*)(asrc);
        aV1 = *(const uint4*)(asrc + 8);
    } else {
        aV0 = make_uint4(0, 0, 0, 0); aV1 = aV0;
    }
    #pragma unroll
    for (int j = 0; j < 16; j++)
        bV[j] = *(const uint16_t*)(bsrc + (size_t)(bkq * 16 + j) * MD);

    for (int it = 0; it < NI; it++) {
        // store A (8 pair-slots = 2 uint4)
        {
            int pb = arow * SSTR + ahalf * 8;
            *(uint4*)&sA[pb]     = aV0;
            *(uint4*)&sA[pb + 4] = aV1;
        }
        // store B (pack k-pairs)
        {
            int pb = bn * SSTR + bkq * 8;
            #pragma unroll
            for (int p = 0; p < 8; p++)
                sB[pb + p] = (uint32_t)bV[2 * p] | ((uint32_t)bV[2 * p + 1] << 16);
        }
        __syncthreads();
        if (it + 1 < NI) {
            int k0 = (it + 1) * 32;
            if (atok >= 0) {
                aV0 = *(const uint4*)(asrc + k0);
                aV1 = *(const uint4*)(asrc + k0 + 8);
            }
            #pragma unroll
            for (int j = 0; j < 16; j++)
                bV[j] = *(const uint16_t*)(bsrc + (size_t)(k0 + bkq * 16 + j) * MD);
        }
        warp_step(sAaddr, sBaddr, m0, n0, lane, acc);
        __syncthreads();
    }

    #pragma unroll
    for (int mt = 0; mt < 4; mt++) {
        int r = row0 + m0 + mt * 16 + gid;
        #pragma unroll
        for (int nt = 0; nt < 4; nt++) {
            int col = col0 + n0 + nt * 8 + tig * 2;
            float bb0 = b1[e * MD + col], bb1 = b1[e * MD + col + 1];
            uint32_t lo = pack2h(fmaxf(acc[mt][nt][0] + bb0, 0.f),
                                 fmaxf(acc[mt][nt][1] + bb1, 0.f));
            uint32_t hi = pack2h(fmaxf(acc[mt][nt][2] + bb0, 0.f),
                                 fmaxf(acc[mt][nt][3] + bb1, 0.f));
            *(uint32_t*)&g_Hh[(size_t)r * MD + col]       = lo;
            *(uint32_t*)&g_Hh[(size_t)(r + 8) * MD + col] = hi;
        }
    }
}

// ---------------- fc2: out[tok] += w * (g_Hh @ W2h + b2) --------------------
__global__ __launch_bounds__(256) void fc2_kernel(
    const float* __restrict__ b2, float* __restrict__ out)
{
    __shared__ __align__(16) uint32_t sA[128 * SSTR];
    __shared__ __align__(16) uint32_t sB[128 * SSTR];
    __shared__ int   stok[128];
    __shared__ float sw[128];

    int tid = threadIdx.x, wid = tid >> 5, lane = tid & 31;
    int gid = lane >> 2, tig = lane & 3;
    int m0 = (wid >> 2) * 64, n0 = (wid & 3) * 32;
    int row0 = blockIdx.y * 128, col0 = blockIdx.x * 128;

    int e = 0;
    while (e < NE - 1 && g_offsets[e + 1] <= row0) e++;
    if (tid < 128) {
        stok[tid] = g_slot_token[row0 + tid];
        sw[tid]   = g_slot_w[row0 + tid];
    }
    __syncthreads();

    uint32_t sAaddr = smem_u32(sA), sBaddr = smem_u32(sB);
    int arow = tid >> 1, ahalf = tid & 1;
    const __half* asrc = g_Hh + (size_t)(row0 + arow) * MD + ahalf * 16;
    int bn = tid & 127, bkq = tid >> 7;
    const __half* bsrc = g_W2h + (size_t)e * MD * HD + col0 + bn;

    float acc[4][4][4];
    #pragma unroll
    for (int mt = 0; mt < 4; mt++)
        #pragma unroll
        for (int nt = 0; nt < 4; nt++)
            #pragma unroll
            for (int j = 0; j < 4; j++) acc[mt][nt][j] = 0.f;

    uint4 aV0, aV1;
    uint16_t bV[16];
    const int NI = MD / 32;

    aV0 = *(const uint4*)(asrc);
    aV1 = *(const uint4*)(asrc + 8);
    #pragma unroll
    for (int j = 0; j < 16; j++)
        bV[j] = *(const uint16_t*)(bsrc + (size_t)(bkq * 16 + j) * HD);

    for (int it = 0; it < NI; it++) {
        {
            int pb = arow * SSTR + ahalf * 8;
            *(uint4*)&sA[pb]     = aV0;
            *(uint4*)&sA[pb + 4] = aV1;
        }
        {
            int pb = bn * SSTR + bkq * 8;
            #pragma unroll
            for (int p = 0; p < 8; p++)
                sB[pb + p] = (uint32_t)bV[2 * p] | ((uint32_t)bV[2 * p + 1] << 16);
        }
        __syncthreads();
        if (it + 1 < NI) {
            int k0 = (it + 1) * 32;
            aV0 = *(const uint4*)(asrc + k0);
            aV1 = *(const uint4*)(asrc + k0 + 8);
            #pragma unroll
            for (int j = 0; j < 16; j++)
                bV[j] = *(const uint16_t*)(bsrc + (size_t)(k0 + bkq * 16 + j) * HD);
        }
        warp_step(sAaddr, sBaddr, m0, n0, lane, acc);
        __syncthreads();
    }

    #pragma unroll
    for (int mt = 0; mt < 4; mt++) {
        int rA = m0 + mt * 16 + gid, rB = rA + 8;
        int tokA = stok[rA], tokB = stok[rB];
        float wA = sw[rA], wB = sw[rB];
        #pragma unroll
        for (int nt = 0; nt < 4; nt++) {
            int col = col0 + n0 + nt * 8 + tig * 2;
            float bb0 = b2[e * HD + col], bb1 = b2[e * HD + col + 1];
            if (tokA >= 0) {
                float* op = out + (size_t)tokA * HD + col;
                atomicAdd(op,     wA * (acc[mt][nt][0] + bb0));
                atomicAdd(op + 1, wA * (acc[mt][nt][1] + bb1));
            }
            if (tokB >= 0) {
                float* op = out + (size_t)tokB * HD + col;
                atomicAdd(op,     wB * (acc[mt][nt][2] + bb0));
                atomicAdd(op + 1, wB * (acc[mt][nt][3] + bb1));
            }
        }
    }
}

// ---------------- launch ----------------------------------------------------
extern "C" void kernel_launch(void* const* d_in, const int* in_sizes, int n_in,
                              void* d_out, int out_size)
{
    const float* X  = (const float*)d_in[0];
    const float* Wg = (const float*)d_in[1];
    const float* bg = (const float*)d_in[2];
    const float* W1 = (const float*)d_in[3];
    const float* b1 = (const float*)d_in[4];
    const float* W2 = (const float*)d_in[5];
    const float* b2 = (const float*)d_in[6];
    float* out = (float*)d_out;

    cudaMemsetAsync(out, 0, sizeof(float) * (size_t)NTOK * HD);

    // one-time-per-launch fp16 conversion (same layout, elementwise)
    {
        __half* w1h; cudaGetSymbolAddress((void**)&w1h, g_W1h);
        __half* w2h; cudaGetSymbolAddress((void**)&w2h, g_W2h);
        __half* xh;  cudaGetSymbolAddress((void**)&xh,  g_Xh);
        int nW = (int)((size_t)NE * HD * MD / 4);   // 8388608
        int nX = (int)((size_t)NTOK * HD / 4);      // 4194304
        f2h_kernel<<<(nW + 255) / 256, 256>>>(W1, w1h, nW);
        f2h_kernel<<<(nW + 255) / 256, 256>>>(W2, w2h, nW);
        f2h_kernel<<<(nX + 255) / 256, 256>>>(X,  xh,  nX);
    }

    init_kernel<<<(MAXSLOTS + 255) / 256, 256>>>();
    gate_kernel<<<(NTOK * 32 + 255) / 256, 256>>>(X, Wg, bg);
    scan_kernel<<<1, 1>>>();
    scatter_kernel<<<(NTOK + 255) / 256, 256>>>();

    fc1_kernel<<<dim3(MD / 128, ROWT), 256>>>(b1);
    fc2_kernel<<<dim3(HD / 128, ROWT), 256>>>(b2, out);
}

// round 13
// speedup vs baseline: 4.7475x; 1.0076x over previous
#include <cuda_runtime.h>
#include <cuda_fp16.h>
#include <cstdint>
#include <math.h>

#define NTOK   16384
#define HD     1024
#define MD     2048
#define NE     16
#define SEGALN 128
#define MAXSLOTS (2*NTOK + NE*SEGALN)   // 34816
#define ROWT     (MAXSLOTS/128)         // 272
#define SSTR   20                       // smem pair-stride (16 pairs + 4 pad; 80B rows)

// ---------------- device scratch ----------------
__device__ int   g_counts[NE];
__device__ int   g_cursor[NE];
__device__ int   g_offsets[NE + 1];
__device__ int   g_slot_token[MAXSLOTS];
__device__ float g_slot_w[MAXSLOTS];
__device__ int   g_top_idx[NTOK * 2];
__device__ float g_top_w[NTOK * 2];
__device__ __half g_Xh [(size_t)NTOK * HD];        // X pre-rounded to fp16
__device__ __half g_W1h[(size_t)NE * HD * MD];     // W1 fp16, same layout
__device__ __half g_W2h[(size_t)NE * MD * HD];     // W2 fp16, same layout
__device__ __half g_Hh [(size_t)MAXSLOTS * MD];    // fc1 output, fp16

// ---------------- helpers ----------------
__device__ __forceinline__ uint32_t smem_u32(const void* p) {
    uint32_t a;
    asm("{ .reg .u64 t; cvta.to.shared.u64 t, %1; cvt.u32.u64 %0, t; }" : "=r"(a) : "l"(p));
    return a;
}
__device__ __forceinline__ uint32_t pack2h(float f0, float f1) {
    __half2 h = __floats2half2_rn(f0, f1);
    return *(uint32_t*)&h;
}
__device__ __forceinline__ void mma_f16(float* c, const uint32_t* a, const uint32_t* b) {
    asm volatile("mma.sync.aligned.m16n8k16.row.col.f32.f16.f16.f32 "
        "{%0,%1,%2,%3},{%4,%5,%6,%7},{%8,%9},{%0,%1,%2,%3};"
        : "+f"(c[0]), "+f"(c[1]), "+f"(c[2]), "+f"(c[3])
        : "r"(a[0]), "r"(a[1]), "r"(a[2]), "r"(a[3]), "r"(b[0]), "r"(b[1]));
}
__device__ __forceinline__ void ldsm4(uint32_t& r0, uint32_t& r1, uint32_t& r2, uint32_t& r3,
                                      uint32_t addr) {
    asm volatile("ldmatrix.sync.aligned.m8n8.x4.shared.b16 {%0,%1,%2,%3}, [%4];"
        : "=r"(r0), "=r"(r1), "=r"(r2), "=r"(r3) : "r"(addr));
}

// ---------------- prep: fp32 -> fp16 elementwise ----------------------------
__global__ __launch_bounds__(256) void f2h_kernel(
    const float* __restrict__ src, __half* __restrict__ dst, int n4)
{
    int i = blockIdx.x * blockDim.x + threadIdx.x;
    if (i >= n4) return;
    float4 v = ((const float4*)src)[i];
    uint2 o;
    o.x = pack2h(v.x, v.y);
    o.y = pack2h(v.z, v.w);
    ((uint2*)dst)[i] = o;
}

// ---------------- routing kernels (verified, unchanged) ---------------------
__global__ void init_kernel() {
    int i = blockIdx.x * blockDim.x + threadIdx.x;
    if (i < MAXSLOTS) g_slot_token[i] = -1;
    if (i < NE) g_counts[i] = 0;
}

__global__ __launch_bounds__(256) void gate_kernel(
    const float* __restrict__ X, const float* __restrict__ Wg,
    const float* __restrict__ bg)
{
    int warp = (blockIdx.x * blockDim.x + threadIdx.x) >> 5;
    int lane = threadIdx.x & 31;
    if (warp >= NTOK) return;
    const float* x = X + (size_t)warp * HD;

    float acc[NE];
    #pragma unroll
    for (int e = 0; e < NE; e++) acc[e] = 0.f;
    for (int h = lane; h < HD; h += 32) {
        float xv = x[h];
        const float* wr = Wg + h * NE;
        #pragma unroll
        for (int e = 0; e < NE; e++) acc[e] += xv * wr[e];
    }
    #pragma unroll
    for (int off = 16; off > 0; off >>= 1)
        #pragma unroll
        for (int e = 0; e < NE; e++)
            acc[e] += __shfl_down_sync(0xffffffffu, acc[e], off);
    if (lane == 0) {
        float lg[NE];
        #pragma unroll
        for (int e = 0; e < NE; e++) lg[e] = acc[e] + bg[e];
        int e0 = 0;
        #pragma unroll
        for (int e = 1; e < NE; e++) if (lg[e] > lg[e0]) e0 = e;
        int e1 = (e0 == 0) ? 1 : 0;
        #pragma unroll
        for (int e = 0; e < NE; e++)
            if (e != e0 && lg[e] > lg[e1]) e1 = e;
        float d = expf(lg[e1] - lg[e0]);
        float w0 = 1.0f / (1.0f + d);
        g_top_idx[2 * warp + 0] = e0;  g_top_w[2 * warp + 0] = w0;
        g_top_idx[2 * warp + 1] = e1;  g_top_w[2 * warp + 1] = 1.0f - w0;
        atomicAdd(&g_counts[e0], 1);
        atomicAdd(&g_counts[e1], 1);
    }
}

__global__ void scan_kernel() {
    int off = 0;
    for (int e = 0; e < NE; e++) {
        g_offsets[e] = off;
        g_cursor[e]  = off;
        off = (off + g_counts[e] + (SEGALN - 1)) & ~(SEGALN - 1);
    }
    g_offsets[NE] = off;
}

__global__ void scatter_kernel() {
    int t = blockIdx.x * blockDim.x + threadIdx.x;
    if (t >= NTOK) return;
    #pragma unroll
    for (int k = 0; k < 2; k++) {
        int e = g_top_idx[2 * t + k];
        int pos = atomicAdd(&g_cursor[e], 1);
        g_slot_token[pos] = t;
        g_slot_w[pos]     = g_top_w[2 * t + k];
    }
}

// ---------------- GEMM machinery: 128x128x32, 8 warps (2m x 4n) -------------
// Double-buffered smem; A and B fp16 in global; smem stores are plain copies.

#define BUFU (128 * SSTR)   // uint32 per plane

// warp compute: one BK=32 chunk, warp tile 64(M) x 32(N), acc[4][4][4]
__device__ __forceinline__ void warp_step(
    uint32_t sAaddr, uint32_t sBaddr,
    int m0, int n0, int lane, float acc[4][4][4])
{
    int l7 = lane & 7;
    int aRow = l7 + ((lane >> 3) & 1) * 8;
    int aKp  = (lane >> 4) * 4;
    int bRow = ((lane >> 4) * 8) + l7;
    int bKp  = ((lane >> 3) & 1) * 4;
    #pragma unroll
    for (int s = 0; s < 2; s++) {
        uint32_t af[4][4], bf[4][2];
        #pragma unroll
        for (int mt = 0; mt < 4; mt++) {
            uint32_t addr = sAaddr + (uint32_t)(((m0 + mt * 16 + aRow) * SSTR) + s * 8 + aKp) * 4u;
            ldsm4(af[mt][0], af[mt][1], af[mt][2], af[mt][3], addr);
        }
        #pragma unroll
        for (int ntp = 0; ntp < 2; ntp++) {
            uint32_t addr = sBaddr + (uint32_t)(((n0 + ntp * 16 + bRow) * SSTR) + s * 8 + bKp) * 4u;
            ldsm4(bf[2 * ntp][0], bf[2 * ntp][1], bf[2 * ntp + 1][0], bf[2 * ntp + 1][1], addr);
        }
        #pragma unroll
        for (int mt = 0; mt < 4; mt++)
            #pragma unroll
            for (int nt = 0; nt < 4; nt++)
                mma_f16(acc[mt][nt], af[mt], bf[nt]);
    }
}

// ---------------- fc1: g_Hh = fp16(relu(gather(Xh) @ W1h + b1)) -------------
__global__ __launch_bounds__(256) void fc1_kernel(
    const float* __restrict__ b1)
{
    __shared__ __align__(16) uint32_t sA[2 * BUFU];
    __shared__ __align__(16) uint32_t sB[2 * BUFU];
    __shared__ int stok[128];

    int tid = threadIdx.x, wid = tid >> 5, lane = tid & 31;
    int gid = lane >> 2, tig = lane & 3;
    int m0 = (wid >> 2) * 64, n0 = (wid & 3) * 32;
    int row0 = blockIdx.y * 128, col0 = blockIdx.x * 128;

    int e = 0;
    while (e < NE - 1 && g_offsets[e + 1] <= row0) e++;
    if (tid < 128) stok[tid] = g_slot_token[row0 + tid];
    __syncthreads();

    uint32_t sAaddr = smem_u32(sA), sBaddr = smem_u32(sB);
    int arow = tid >> 1, ahalf = tid & 1;
    int atok = stok[arow];
    const __half* asrc = g_Xh + (size_t)(atok < 0 ? 0 : atok) * HD + ahalf * 16;
    int bn = tid & 127, bkq = tid >> 7;
    const __half* bsrc = g_W1h + (size_t)e * HD * MD + col0 + bn;
    int aPb = arow * SSTR + ahalf * 8;
    int bPb = bn * SSTR + bkq * 8;

    float acc[4][4][4];
    #pragma unroll
    for (int mt = 0; mt < 4; mt++)
        #pragma unroll
        for (int nt = 0; nt < 4; nt++)
            #pragma unroll
            for (int j = 0; j < 4; j++) acc[mt][nt][j] = 0.f;

    uint4 aV0, aV1;
    uint16_t bV[16];
    const int NI = HD / 32;

    // prologue: chunk 0 -> buf 0
    if (atok >= 0) {
        aV0 = *(const uint4*)(asrc);
        aV1 = *(const uint4*)(asrc + 8);
    } else {
        aV0 = make_uint4(0, 0, 0, 0); aV1 = aV0;
    }
    #pragma unroll
    for (int j = 0; j < 16; j++)
        bV[j] = *(const uint16_t*)(bsrc + (size_t)(bkq * 16 + j) * MD);
    *(uint4*)&sA[aPb]     = aV0;
    *(uint4*)&sA[aPb + 4] = aV1;
    #pragma unroll
    for (int p = 0; p < 8; p++)
        sB[bPb + p] = (uint32_t)bV[2 * p] | ((uint32_t)bV[2 * p + 1] << 16);
    __syncthreads();

    for (int it = 0; it < NI; it++) {
        int buf = it & 1, nbuf = buf ^ 1;
        bool more = (it + 1 < NI);
        if (more) {
            int k0 = (it + 1) * 32;
            if (atok >= 0) {
                aV0 = *(const uint4*)(asrc + k0);
                aV1 = *(const uint4*)(asrc + k0 + 8);
            }
            #pragma unroll
            for (int j = 0; j < 16; j++)
                bV[j] = *(const uint16_t*)(bsrc + (size_t)(k0 + bkq * 16 + j) * MD);
        }
        warp_step(sAaddr + (uint32_t)buf * BUFU * 4u,
                  sBaddr + (uint32_t)buf * BUFU * 4u, m0, n0, lane, acc);
        if (more) {
            uint32_t* dA = sA + nbuf * BUFU;
            uint32_t* dB = sB + nbuf * BUFU;
            *(uint4*)&dA[aPb]     = aV0;
            *(uint4*)&dA[aPb + 4] = aV1;
            #pragma unroll
            for (int p = 0; p < 8; p++)
                dB[bPb + p] = (uint32_t)bV[2 * p] | ((uint32_t)bV[2 * p + 1] << 16);
        }
        __syncthreads();
    }

    #pragma unroll
    for (int mt = 0; mt < 4; mt++) {
        int r = row0 + m0 + mt * 16 + gid;
        #pragma unroll
        for (int nt = 0; nt < 4; nt++) {
            int col = col0 + n0 + nt * 8 + tig * 2;
            float bb0 = b1[e * MD + col], bb1 = b1[e * MD + col + 1];
            uint32_t lo = pack2h(fmaxf(acc[mt][nt][0] + bb0, 0.f),
                                 fmaxf(acc[mt][nt][1] + bb1, 0.f));
            uint32_t hi = pack2h(fmaxf(acc[mt][nt][2] + bb0, 0.f),
                                 fmaxf(acc[mt][nt][3] + bb1, 0.f));
            *(uint32_t*)&g_Hh[(size_t)r * MD + col]       = lo;
            *(uint32_t*)&g_Hh[(size_t)(r + 8) * MD + col] = hi;
        }
    }
}

// ---------------- fc2: out[tok] += w * (g_Hh @ W2h + b2) --------------------
__global__ __launch_bounds__(256) void fc2_kernel(
    const float* __restrict__ b2, float* __restrict__ out)
{
    __shared__ __align__(16) uint32_t sA[2 * BUFU];
    __shared__ __align__(16) uint32_t sB[2 * BUFU];
    __shared__ int   stok[128];
    __shared__ float sw[128];

    int tid = threadIdx.x, wid = tid >> 5, lane = tid & 31;
    int gid = lane >> 2, tig = lane & 3;
    int m0 = (wid >> 2) * 64, n0 = (wid & 3) * 32;
    int row0 = blockIdx.y * 128, col0 = blockIdx.x * 128;

    int e = 0;
    while (e < NE - 1 && g_offsets[e + 1] <= row0) e++;
    if (tid < 128) {
        stok[tid] = g_slot_token[row0 + tid];
        sw[tid]   = g_slot_w[row0 + tid];
    }
    __syncthreads();

    uint32_t sAaddr = smem_u32(sA), sBaddr = smem_u32(sB);
    int arow = tid >> 1, ahalf = tid & 1;
    const __half* asrc = g_Hh + (size_t)(row0 + arow) * MD + ahalf * 16;
    int bn = tid & 127, bkq = tid >> 7;
    const __half* bsrc = g_W2h + (size_t)e * MD * HD + col0 + bn;
    int aPb = arow * SSTR + ahalf * 8;
    int bPb = bn * SSTR + bkq * 8;

    float acc[4][4][4];
    #pragma unroll
    for (int mt = 0; mt < 4; mt++)
        #pragma unroll
        for (int nt = 0; nt < 4; nt++)
            #pragma unroll
            for (int j = 0; j < 4; j++) acc[mt][nt][j] = 0.f;

    uint4 aV0, aV1;
    uint16_t bV[16];
    const int NI = MD / 32;

    aV0 = *(const uint4*)(asrc);
    aV1 = *(const uint4*)(asrc + 8);
    #pragma unroll
    for (int j = 0; j < 16; j++)
        bV[j] = *(const uint16_t*)(bsrc + (size_t)(bkq * 16 + j) * HD);
    *(uint4*)&sA[aPb]     = aV0;
    *(uint4*)&sA[aPb + 4] = aV1;
    #pragma unroll
    for (int p = 0; p < 8; p++)
        sB[bPb + p] = (uint32_t)bV[2 * p] | ((uint32_t)bV[2 * p + 1] << 16);
    __syncthreads();

    for (int it = 0; it < NI; it++) {
        int buf = it & 1, nbuf = buf ^ 1;
        bool more = (it + 1 < NI);
        if (more) {
            int k0 = (it + 1) * 32;
            aV0 = *(const uint4*)(asrc + k0);
            aV1 = *(const uint4*)(asrc + k0 + 8);
            #pragma unroll
            for (int j = 0; j < 16; j++)
                bV[j] = *(const uint16_t*)(bsrc + (size_t)(k0 + bkq * 16 + j) * HD);
        }
        warp_step(sAaddr + (uint32_t)buf * BUFU * 4u,
                  sBaddr + (uint32_t)buf * BUFU * 4u, m0, n0, lane, acc);
        if (more) {
            uint32_t* dA = sA + nbuf * BUFU;
            uint32_t* dB = sB + nbuf * BUFU;
            *(uint4*)&dA[aPb]     = aV0;
            *(uint4*)&dA[aPb + 4] = aV1;
            #pragma unroll
            for (int p = 0; p < 8; p++)
                dB[bPb + p] = (uint32_t)bV[2 * p] | ((uint32_t)bV[2 * p + 1] << 16);
        }
        __syncthreads();
    }

    #pragma unroll
    for (int mt = 0; mt < 4; mt++) {
        int rA = m0 + mt * 16 + gid, rB = rA + 8;
        int tokA = stok[rA], tokB = stok[rB];
        float wA = sw[rA], wB = sw[rB];
        #pragma unroll
        for (int nt = 0; nt < 4; nt++) {
            int col = col0 + n0 + nt * 8 + tig * 2;
            float bb0 = b2[e * HD + col], bb1 = b2[e * HD + col + 1];
            if (tokA >= 0) {
                float* op = out + (size_t)tokA * HD + col;
                atomicAdd(op,     wA * (acc[mt][nt][0] + bb0));
                atomicAdd(op + 1, wA * (acc[mt][nt][1] + bb1));
            }
            if (tokB >= 0) {
                float* op = out + (size_t)tokB * HD + col;
                atomicAdd(op,     wB * (acc[mt][nt][2] + bb0));
                atomicAdd(op + 1, wB * (acc[mt][nt][3] + bb1));
            }
        }
    }
}

// ---------------- launch ----------------------------------------------------
extern "C" void kernel_launch(void* const* d_in, const int* in_sizes, int n_in,
                              void* d_out, int out_size)
{
    const float* X  = (const float*)d_in[0];
    const float* Wg = (const float*)d_in[1];
    const float* bg = (const float*)d_in[2];
    const float* W1 = (const float*)d_in[3];
    const float* b1 = (const float*)d_in[4];
    const float* W2 = (const float*)d_in[5];
    const float* b2 = (const float*)d_in[6];
    float* out = (float*)d_out;

    cudaMemsetAsync(out, 0, sizeof(float) * (size_t)NTOK * HD);

    {
        __half* w1h; cudaGetSymbolAddress((void**)&w1h, g_W1h);
        __half* w2h; cudaGetSymbolAddress((void**)&w2h, g_W2h);
        __half* xh;  cudaGetSymbolAddress((void**)&xh,  g_Xh);
        int nW = (int)((size_t)NE * HD * MD / 4);   // 8388608
        int nX = (int)((size_t)NTOK * HD / 4);      // 4194304
        f2h_kernel<<<(nW + 255) / 256, 256>>>(W1, w1h, nW);
        f2h_kernel<<<(nW + 255) / 256, 256>>>(W2, w2h, nW);
        f2h_kernel<<<(nX + 255) / 256, 256>>>(X,  xh,  nX);
    }

    init_kernel<<<(MAXSLOTS + 255) / 256, 256>>>();
    gate_kernel<<<(NTOK * 32 + 255) / 256, 256>>>(X, Wg, bg);
    scan_kernel<<<1, 1>>>();
    scatter_kernel<<<(NTOK + 255) / 256, 256>>>();

    fc1_kernel<<<dim3(MD / 128, ROWT), 256>>>(b1);
    fc2_kernel<<<dim3(HD / 128, ROWT), 256>>>(b2, out);
}